// round 7
// baseline (speedup 1.0000x reference)
#include <cuda_runtime.h>
#include <cuda_fp16.h>
#include <math.h>
#include <stdint.h>

// ---------------- problem constants ----------------
#define D_MODEL 768
#define N_HEADS 12
#define D_HEAD  64
#define D_MLP   3072
#define BATCH   2
#define SEQ     2048
#define ROWS    (BATCH*SEQ)          // 4096
#define QKV_N   (3*D_MODEL)          // 2304

// ---------------- device scratch ----------------
__device__ __half g_x1h   [ROWS * D_MODEL];
__device__ __half g_qkvh  [ROWS * QKV_N];
__device__ __half g_zh    [ROWS * D_MODEL];
__device__ float  g_mid   [ROWS * D_MODEL];
__device__ __half g_x2h   [ROWS * D_MODEL];
__device__ __half g_hidh  [ROWS * D_MLP];
__device__ __half g_wqkvh [D_MODEL * QKV_N];
__device__ float  g_bqkv  [QKV_N];
__device__ __half g_woh   [D_MODEL * D_MODEL];
__device__ __half g_winh  [D_MODEL * D_MLP];
__device__ __half g_wouth [D_MLP * D_MODEL];

// ---------------- helpers ----------------
__device__ __forceinline__ uint32_t smem_u32(const void* p) {
    uint32_t a;
    asm("{ .reg .u64 t; cvta.to.shared.u64 t, %1; cvt.u32.u64 %0, t; }" : "=r"(a) : "l"(p));
    return a;
}
__device__ __forceinline__ float fast_tanh(float x) {
    float y; asm("tanh.approx.f32 %0, %1;" : "=f"(y) : "f"(x)); return y;
}
__device__ __forceinline__ float gelu_new_f(float x) {
    const float c = 0.7978845608028654f;
    float x3 = x * x * x;
    return 0.5f * x * (1.0f + fast_tanh(c * (x + 0.044715f * x3)));
}
__device__ __forceinline__ void mma_f16(float& c0, float& c1, float& c2, float& c3,
                                        uint32_t a0, uint32_t a1, uint32_t a2, uint32_t a3,
                                        uint32_t b0, uint32_t b1) {
    asm volatile(
        "mma.sync.aligned.m16n8k16.row.col.f32.f16.f16.f32 "
        "{%0,%1,%2,%3}, {%4,%5,%6,%7}, {%8,%9}, {%0,%1,%2,%3};\n"
        : "+f"(c0), "+f"(c1), "+f"(c2), "+f"(c3)
        : "r"(a0), "r"(a1), "r"(a2), "r"(a3), "r"(b0), "r"(b1));
}
__device__ __forceinline__ void ldm_x4(uint32_t& r0, uint32_t& r1, uint32_t& r2, uint32_t& r3,
                                       uint32_t a) {
    asm volatile("ldmatrix.sync.aligned.m8n8.x4.shared.b16 {%0,%1,%2,%3}, [%4];"
                 : "=r"(r0), "=r"(r1), "=r"(r2), "=r"(r3) : "r"(a));
}
__device__ __forceinline__ void ldm_x4t(uint32_t& r0, uint32_t& r1, uint32_t& r2, uint32_t& r3,
                                        uint32_t a) {
    asm volatile("ldmatrix.sync.aligned.m8n8.x4.trans.shared.b16 {%0,%1,%2,%3}, [%4];"
                 : "=r"(r0), "=r"(r1), "=r"(r2), "=r"(r3) : "r"(a));
}
__device__ __forceinline__ void cp16(uint32_t dst, const void* src) {
    asm volatile("cp.async.cg.shared.global [%0], [%1], 16;" :: "r"(dst), "l"(src));
}
#define CP_COMMIT() asm volatile("cp.async.commit_group;" ::: "memory")
#define CP_WAIT1()  asm volatile("cp.async.wait_group 1;" ::: "memory")
#define CP_WAIT0()  asm volatile("cp.async.wait_group 0;" ::: "memory")

__device__ __forceinline__ uint32_t h2u(__half2 h) { return *(uint32_t*)&h; }

__device__ __forceinline__ float block_sum256(float v) {
    __shared__ float red[8];
    __shared__ float total;
    #pragma unroll
    for (int m = 16; m >= 1; m >>= 1) v += __shfl_xor_sync(0xffffffffu, v, m);
    int w = threadIdx.x >> 5;
    if ((threadIdx.x & 31) == 0) red[w] = v;
    __syncthreads();
    if (threadIdx.x < 8) {
        float t = red[threadIdx.x];
        t += __shfl_xor_sync(0xffu, t, 4);
        t += __shfl_xor_sync(0xffu, t, 2);
        t += __shfl_xor_sync(0xffu, t, 1);
        if (threadIdx.x == 0) total = t;
    }
    __syncthreads();
    return total;
}

// ---------------- weight prep -----------------------------------------------------
__global__ void pack_qkv_h(const float* __restrict__ WQ, const float* __restrict__ WK,
                           const float* __restrict__ WV, const float* __restrict__ bQ,
                           const float* __restrict__ bK, const float* __restrict__ bV,
                           __half* __restrict__ Wp, float* __restrict__ bp) {
    int idx = blockIdx.x * blockDim.x + threadIdx.x;
    if (idx < D_MODEL * QKV_N) {
        int e = idx / QKV_N;
        int col = idx - e * QKV_N;
        int which = col / D_MODEL;
        int c = col - which * D_MODEL;
        int n = c >> 6;
        int hd = c & 63;
        const float* W = (which == 0) ? WQ : (which == 1) ? WK : WV;
        Wp[idx] = __float2half_rn(W[((size_t)n * D_MODEL + e) * D_HEAD + hd]);
    }
    if (idx < QKV_N) {
        int which = idx / D_MODEL;
        int c = idx - which * D_MODEL;
        const float* bb = (which == 0) ? bQ : (which == 1) ? bK : bV;
        bp[idx] = bb[c];
    }
}

__global__ void f2h(const float* __restrict__ s, __half* __restrict__ d, int n8) {
    int i = blockIdx.x * 256 + threadIdx.x;
    if (i < n8) {
        float4 v0 = *(const float4*)(s + (size_t)i * 8);
        float4 v1 = *(const float4*)(s + (size_t)i * 8 + 4);
        __half2 h[4];
        h[0] = __floats2half2_rn(v0.x, v0.y);
        h[1] = __floats2half2_rn(v0.z, v0.w);
        h[2] = __floats2half2_rn(v1.x, v1.y);
        h[3] = __floats2half2_rn(v1.z, v1.w);
        *(uint4*)(d + (size_t)i * 8) = *(uint4*)h;
    }
}

// ---------------- layernorm: fp32 in, fp16 out ----------------------------------
__global__ void ln_kernel_h(const float* __restrict__ x, const float* __restrict__ w,
                            const float* __restrict__ b, __half* __restrict__ y) {
    int row = blockIdx.x;
    const float* xr = x + (size_t)row * D_MODEL;
    __half* yr = y + (size_t)row * D_MODEL;
    int tid = threadIdx.x;
    float v0 = xr[tid], v1 = xr[tid + 256], v2 = xr[tid + 512];
    float s = block_sum256(v0 + v1 + v2);
    float mean = s * (1.0f / D_MODEL);
    float d0 = v0 - mean, d1 = v1 - mean, d2 = v2 - mean;
    float sq = block_sum256(d0 * d0 + d1 * d1 + d2 * d2);
    float rstd = rsqrtf(sq * (1.0f / D_MODEL) + 1e-5f);
    yr[tid]       = __float2half_rn(d0 * rstd * w[tid]       + b[tid]);
    yr[tid + 256] = __float2half_rn(d1 * rstd * w[tid + 256] + b[tid + 256]);
    yr[tid + 512] = __float2half_rn(d2 * rstd * w[tid + 512] + b[tid + 512]);
}

// ---------------- fp16 tensor-core GEMM (unchanged from R6) ----------------------
#define GH_STG 32768
#define GH_SMEM (3 * GH_STG)

template<int GELU, int RES, int OUTH>
__global__ __launch_bounds__(256, 2) void gemm_h(
        const __half* __restrict__ A, const __half* __restrict__ B,
        const float* __restrict__ bias, const float* __restrict__ res,
        void* __restrict__ Cv, int M, int N, int K) {
    extern __shared__ char sm8[];
    const uint32_t sb = smem_u32(sm8);

    const int tid = threadIdx.x;
    const int lane = tid & 31;
    const int wid = tid >> 5;
    const int lr = lane >> 2;
    const int lc = lane & 3;
    const int warp_m = wid & 1;
    const int warp_n = wid >> 1;
    const int bm = blockIdx.y * 128;
    const int bn = blockIdx.x * 128;

    float acc[4][4][4];
    #pragma unroll
    for (int i = 0; i < 4; i++)
        #pragma unroll
        for (int j = 0; j < 4; j++)
            #pragma unroll
            for (int u = 0; u < 4; u++) acc[i][j][u] = 0.0f;

    const int nt = K / 64;

    auto issue = [&](int s, int bk) {
        uint32_t ab = sb + (uint32_t)s * GH_STG;
        #pragma unroll
        for (int i = 0; i < 4; i++) {
            int idx = tid + i * 256;
            int rr = idx >> 3, c = idx & 7;
            cp16(ab + (uint32_t)(rr * 128 + ((c ^ (rr & 7)) * 16)),
                 A + (size_t)(bm + rr) * K + bk + c * 8);
        }
        uint32_t bb = ab + 16384;
        #pragma unroll
        for (int i = 0; i < 4; i++) {
            int idx = tid + i * 256;
            int rr = idx >> 4, c = idx & 15;
            int sc = (c & 8) | ((c ^ rr) & 7);
            cp16(bb + (uint32_t)(rr * 256 + sc * 16),
                 B + (size_t)(bk + rr) * N + bn + c * 8);
        }
    };

    issue(0, 0);  CP_COMMIT();
    issue(1, 64); CP_COMMIT();

    const int j8 = lane >> 3;
    const int li = lane & 7;

    for (int t = 0; t < nt; t++) {
        CP_WAIT1();
        __syncthreads();
        if (t + 2 < nt) issue((t + 2) % 3, (t + 2) * 64);
        CP_COMMIT();

        const uint32_t Ab = sb + (uint32_t)(t % 3) * GH_STG;
        const uint32_t Bb = Ab + 16384;

        #pragma unroll
        for (int ks = 0; ks < 4; ks++) {
            uint32_t a[4][4];
            #pragma unroll
            for (int i = 0; i < 4; i++) {
                int row = warp_m * 64 + i * 16 + (j8 & 1) * 8 + li;
                int chunk = ks * 2 + (j8 >> 1);
                ldm_x4(a[i][0], a[i][1], a[i][2], a[i][3],
                       Ab + (uint32_t)(row * 128 + ((chunk ^ (row & 7)) * 16)));
            }
            uint32_t b[2][4];
            #pragma unroll
            for (int jn = 0; jn < 2; jn++) {
                int krow = ks * 16 + (j8 & 1) * 8 + li;
                int nch = warp_n * 4 + jn * 2 + (j8 >> 1);
                int sc = (nch & 8) | ((nch ^ krow) & 7);
                ldm_x4t(b[jn][0], b[jn][1], b[jn][2], b[jn][3],
                        Bb + (uint32_t)(krow * 256 + sc * 16));
            }
            #pragma unroll
            for (int i = 0; i < 4; i++)
                #pragma unroll
                for (int n8 = 0; n8 < 4; n8++) {
                    int jn = n8 >> 1, sub = n8 & 1;
                    mma_f16(acc[i][n8][0], acc[i][n8][1], acc[i][n8][2], acc[i][n8][3],
                            a[i][0], a[i][1], a[i][2], a[i][3],
                            b[jn][sub * 2], b[jn][sub * 2 + 1]);
                }
        }
        __syncthreads();
    }
    CP_WAIT0();

    float* Cf = (float*)Cv;
    __half* Ch = (__half*)Cv;
    #pragma unroll
    for (int i = 0; i < 4; i++) {
        #pragma unroll
        for (int n8 = 0; n8 < 4; n8++) {
            int r0 = bm + warp_m * 64 + i * 16 + lr;
            int cc = bn + warp_n * 32 + n8 * 8 + lc * 2;
            float2 bv = *(const float2*)&bias[cc];
            #pragma unroll
            for (int hrow = 0; hrow < 2; hrow++) {
                int r = r0 + hrow * 8;
                float o0 = acc[i][n8][hrow * 2]     + bv.x;
                float o1 = acc[i][n8][hrow * 2 + 1] + bv.y;
                if (GELU) { o0 = gelu_new_f(o0); o1 = gelu_new_f(o1); }
                if (RES) {
                    float2 rv = *(const float2*)&res[(size_t)r * N + cc];
                    o0 += rv.x; o1 += rv.y;
                }
                if (OUTH) {
                    __half2 h = __floats2half2_rn(o0, o1);
                    *(__half2*)&Ch[(size_t)r * N + cc] = h;
                } else {
                    *(float2*)&Cf[(size_t)r * N + cc] = make_float2(o0, o1);
                }
            }
        }
    }
}

// ---------------- fp16 MMA flash attention ---------------------------------------
// BQ=128, BK=64, 8 warps x 16 q-rows. K/V half in smem (cp.async 3-stage),
// Q in register fragments, P repacked in registers (no smem round-trip).
#define AT_Q   16384                  // Q stage: 128 x 64 half
#define AT_STG 16384                  // K 8KB + V 8KB per stage
#define ATTN_SMEM (AT_Q + 3 * AT_STG) // 64 KB

__global__ __launch_bounds__(256, 2) void attn_h_kernel(const __half* __restrict__ qkv,
                                                        __half* __restrict__ z) {
    const int qt = (SEQ / 128 - 1) - blockIdx.x;
    const int bh = blockIdx.y;
    const int b = bh / N_HEADS;
    const int h = bh - b * N_HEADS;

    extern __shared__ char sm8[];
    const uint32_t sb = smem_u32(sm8);
    const uint32_t stg = sb + AT_Q;

    const int tid = threadIdx.x;
    const int lane = tid & 31;
    const int wid = tid >> 5;
    const int lr = lane >> 2;
    const int lc = lane & 3;
    const int j8 = lane >> 3;
    const int li = lane & 7;

    const size_t rowbase = (size_t)b * SEQ;
    const __half* qb = qkv + rowbase * QKV_N + h * 64;
    const __half* kb = qb + D_MODEL;
    const __half* vb = qb + 2 * D_MODEL;

    // ---- stage Q (scaled 1/8, exact in half) into swizzled smem ----
    {
        const __half2 sc2 = __floats2half2_rn(0.125f, 0.125f);
        #pragma unroll
        for (int i = 0; i < 4; i++) {
            int idx = tid + i * 256;          // 1024 chunks (128 rows x 8)
            int r = idx >> 3, c = idx & 7;
            uint4 raw = *(const uint4*)(qb + (size_t)(qt * 128 + r) * QKV_N + c * 8);
            __half2* hp = (__half2*)&raw;
            hp[0] = __hmul2(hp[0], sc2); hp[1] = __hmul2(hp[1], sc2);
            hp[2] = __hmul2(hp[2], sc2); hp[3] = __hmul2(hp[3], sc2);
            *(uint4*)(sm8 + r * 128 + ((c ^ (r & 7)) * 16)) = raw;
        }
    }
    __syncthreads();

    // ---- Q register fragments: qa[ks][0..3] for k16 steps ks ----
    uint32_t qa[4][4];
    {
        int row = wid * 16 + (j8 & 1) * 8 + li;
        uint32_t rb_ = sb + row * 128;
        #pragma unroll
        for (int ks = 0; ks < 4; ks++) {
            int ch = ks * 2 + (j8 >> 1);
            ldm_x4(qa[ks][0], qa[ks][1], qa[ks][2], qa[ks][3],
                   rb_ + ((ch ^ (row & 7)) * 16));
        }
    }

    const int row0 = qt * 128 + wid * 16 + lr;
    const int row1 = row0 + 8;

    float m0 = -INFINITY, m1 = -INFINITY, l0 = 0.0f, l1 = 0.0f;
    float o[8][4];
    #pragma unroll
    for (int n = 0; n < 8; n++) { o[n][0] = o[n][1] = o[n][2] = o[n][3] = 0.0f; }

    const int nkt = 2 * qt + 2;

    auto issue = [&](int s, int kt) {
        uint32_t base = stg + (uint32_t)s * AT_STG;
        #pragma unroll
        for (int i = 0; i < 2; i++) {
            int idx = tid + i * 256;          // 512 chunks (64 rows x 8)
            int r = idx >> 3, c = idx & 7;
            uint32_t off = r * 128 + ((c ^ (r & 7)) * 16);
            size_t grow = (size_t)(kt * 64 + r) * QKV_N + c * 8;
            cp16(base + off,        kb + grow);
            cp16(base + 8192 + off, vb + grow);
        }
    };

    issue(0, 0); CP_COMMIT();
    issue(1, 1); CP_COMMIT();

    for (int kt = 0; kt < nkt; kt++) {
        CP_WAIT1();
        __syncthreads();
        if (kt + 2 < nkt) issue((kt + 2) % 3, kt + 2);
        CP_COMMIT();

        const uint32_t Kb = stg + (uint32_t)(kt % 3) * AT_STG;
        const uint32_t Vb = Kb + 8192;

        // ---- S = Q K^T (fp16 mma, fp32 acc) ----
        float s[8][4];
        #pragma unroll
        for (int n = 0; n < 8; n++) { s[n][0] = s[n][1] = s[n][2] = s[n][3] = 0.0f; }
        #pragma unroll
        for (int ks = 0; ks < 4; ks++) {
            #pragma unroll
            for (int ng = 0; ng < 4; ng++) {
                int row = ng * 16 + (j8 & 1) * 8 + li;
                int ch = ks * 2 + (j8 >> 1);
                uint32_t k0, k1, k2, k3;
                ldm_x4(k0, k1, k2, k3, Kb + row * 128 + ((ch ^ (row & 7)) * 16));
                mma_f16(s[ng * 2][0], s[ng * 2][1], s[ng * 2][2], s[ng * 2][3],
                        qa[ks][0], qa[ks][1], qa[ks][2], qa[ks][3], k0, k2);
                mma_f16(s[ng * 2 + 1][0], s[ng * 2 + 1][1], s[ng * 2 + 1][2], s[ng * 2 + 1][3],
                        qa[ks][0], qa[ks][1], qa[ks][2], qa[ks][3], k1, k3);
            }
        }

        // ---- causal mask ----
        if (kt >= 2 * qt) {
            const int kbase = kt * 64 + lc * 2;
            #pragma unroll
            for (int n8 = 0; n8 < 8; n8++) {
                int key0 = kbase + n8 * 8;
                int key1 = key0 + 1;
                if (key0 > row0) s[n8][0] = -1e30f;
                if (key1 > row0) s[n8][1] = -1e30f;
                if (key0 > row1) s[n8][2] = -1e30f;
                if (key1 > row1) s[n8][3] = -1e30f;
            }
        }

        // ---- online softmax (fp32) ----
        float tm0 = -INFINITY, tm1 = -INFINITY;
        #pragma unroll
        for (int n8 = 0; n8 < 8; n8++) {
            tm0 = fmaxf(tm0, fmaxf(s[n8][0], s[n8][1]));
            tm1 = fmaxf(tm1, fmaxf(s[n8][2], s[n8][3]));
        }
        tm0 = fmaxf(tm0, __shfl_xor_sync(0xffffffffu, tm0, 1));
        tm0 = fmaxf(tm0, __shfl_xor_sync(0xffffffffu, tm0, 2));
        tm1 = fmaxf(tm1, __shfl_xor_sync(0xffffffffu, tm1, 1));
        tm1 = fmaxf(tm1, __shfl_xor_sync(0xffffffffu, tm1, 2));
        float nm0 = fmaxf(m0, tm0), nm1 = fmaxf(m1, tm1);
        float a0 = __expf(m0 - nm0), a1 = __expf(m1 - nm1);
        m0 = nm0; m1 = nm1;

        float ts0 = 0.0f, ts1 = 0.0f;
        uint32_t ph[8][2];     // P fragments in registers (half2 packs)
        #pragma unroll
        for (int n8 = 0; n8 < 8; n8++) {
            float p0 = __expf(s[n8][0] - nm0);
            float p1 = __expf(s[n8][1] - nm0);
            float p2 = __expf(s[n8][2] - nm1);
            float p3 = __expf(s[n8][3] - nm1);
            ts0 += p0 + p1;
            ts1 += p2 + p3;
            __half2 lo = __floats2half2_rn(p0, p1);
            __half2 hi = __floats2half2_rn(p2, p3);
            ph[n8][0] = h2u(lo);
            ph[n8][1] = h2u(hi);
        }
        ts0 += __shfl_xor_sync(0xffffffffu, ts0, 1);
        ts0 += __shfl_xor_sync(0xffffffffu, ts0, 2);
        ts1 += __shfl_xor_sync(0xffffffffu, ts1, 1);
        ts1 += __shfl_xor_sync(0xffffffffu, ts1, 2);
        l0 = l0 * a0 + ts0;
        l1 = l1 * a1 + ts1;
        #pragma unroll
        for (int n8 = 0; n8 < 8; n8++) {
            o[n8][0] *= a0; o[n8][1] *= a0;
            o[n8][2] *= a1; o[n8][3] *= a1;
        }

        // ---- O += P V (P from registers, V via ldmatrix.trans) ----
        #pragma unroll
        for (int ks = 0; ks < 4; ks++) {
            uint32_t pa0 = ph[ks * 2][0];
            uint32_t pa1 = ph[ks * 2][1];
            uint32_t pa2 = ph[ks * 2 + 1][0];
            uint32_t pa3 = ph[ks * 2 + 1][1];
            #pragma unroll
            for (int vg = 0; vg < 4; vg++) {
                int krow = ks * 16 + (j8 & 1) * 8 + li;
                int nch = vg * 2 + (j8 >> 1);
                uint32_t v0, v1, v2, v3;
                ldm_x4t(v0, v1, v2, v3, Vb + krow * 128 + ((nch ^ (krow & 7)) * 16));
                mma_f16(o[vg * 2][0], o[vg * 2][1], o[vg * 2][2], o[vg * 2][3],
                        pa0, pa1, pa2, pa3, v0, v1);
                mma_f16(o[vg * 2 + 1][0], o[vg * 2 + 1][1], o[vg * 2 + 1][2], o[vg * 2 + 1][3],
                        pa0, pa1, pa2, pa3, v2, v3);
            }
        }
    }
    CP_WAIT0();

    // ---- epilogue ----
    float inv0 = 1.0f / l0, inv1 = 1.0f / l1;
    __half* z0 = z + (rowbase + row0) * D_MODEL + h * 64 + lc * 2;
    __half* z1 = z + (rowbase + row1) * D_MODEL + h * 64 + lc * 2;
    #pragma unroll
    for (int n8 = 0; n8 < 8; n8++) {
        *(__half2*)(z0 + n8 * 8) = __floats2half2_rn(o[n8][0] * inv0, o[n8][1] * inv0);
        *(__half2*)(z1 + n8 * 8) = __floats2half2_rn(o[n8][2] * inv1, o[n8][3] * inv1);
    }
}

// ---------------- launch ----------------
extern "C" void kernel_launch(void* const* d_in, const int* in_sizes, int n_in,
                              void* d_out, int out_size) {
    const float* resid_pre = (const float*)d_in[0];
    const float* WQ   = (const float*)d_in[1];
    const float* bQ   = (const float*)d_in[2];
    const float* WK   = (const float*)d_in[3];
    const float* bK   = (const float*)d_in[4];
    const float* WV   = (const float*)d_in[5];
    const float* bV   = (const float*)d_in[6];
    const float* WO   = (const float*)d_in[7];
    const float* bO   = (const float*)d_in[8];
    const float* ln1w = (const float*)d_in[9];
    const float* ln1b = (const float*)d_in[10];
    const float* ln2w = (const float*)d_in[11];
    const float* ln2b = (const float*)d_in[12];
    const float* Win  = (const float*)d_in[13];
    const float* bin  = (const float*)d_in[14];
    const float* Wout = (const float*)d_in[15];
    const float* bout = (const float*)d_in[16];
    float* out = (float*)d_out;

    __half *x1h, *qkvh, *zh, *x2h, *hidh, *wqkvh, *woh, *winh, *wouth;
    float *mid, *bp;
    cudaGetSymbolAddress((void**)&x1h,    g_x1h);
    cudaGetSymbolAddress((void**)&qkvh,   g_qkvh);
    cudaGetSymbolAddress((void**)&zh,     g_zh);
    cudaGetSymbolAddress((void**)&mid,    g_mid);
    cudaGetSymbolAddress((void**)&x2h,    g_x2h);
    cudaGetSymbolAddress((void**)&hidh,   g_hidh);
    cudaGetSymbolAddress((void**)&wqkvh,  g_wqkvh);
    cudaGetSymbolAddress((void**)&bp,     g_bqkv);
    cudaGetSymbolAddress((void**)&woh,    g_woh);
    cudaGetSymbolAddress((void**)&winh,   g_winh);
    cudaGetSymbolAddress((void**)&wouth,  g_wouth);

    cudaFuncSetAttribute(attn_h_kernel, cudaFuncAttributeMaxDynamicSharedMemorySize, ATTN_SMEM);
    cudaFuncSetAttribute(gemm_h<0,0,1>, cudaFuncAttributeMaxDynamicSharedMemorySize, GH_SMEM);
    cudaFuncSetAttribute(gemm_h<0,1,0>, cudaFuncAttributeMaxDynamicSharedMemorySize, GH_SMEM);
    cudaFuncSetAttribute(gemm_h<1,0,1>, cudaFuncAttributeMaxDynamicSharedMemorySize, GH_SMEM);

    // weight prep
    pack_qkv_h<<<(D_MODEL * QKV_N + 255) / 256, 256>>>(WQ, WK, WV, bQ, bK, bV, wqkvh, bp);
    f2h<<<(D_MODEL * D_MODEL / 8 + 255) / 256, 256>>>(WO,   woh,   D_MODEL * D_MODEL / 8);
    f2h<<<(D_MODEL * D_MLP   / 8 + 255) / 256, 256>>>(Win,  winh,  D_MODEL * D_MLP / 8);
    f2h<<<(D_MLP   * D_MODEL / 8 + 255) / 256, 256>>>(Wout, wouth, D_MLP * D_MODEL / 8);

    // LN1 -> half
    ln_kernel_h<<<ROWS, 256>>>(resid_pre, ln1w, ln1b, x1h);
    // QKV projection -> half
    gemm_h<0,0,1><<<dim3(QKV_N / 128, ROWS / 128), 256, GH_SMEM>>>(
        x1h, wqkvh, bp, nullptr, qkvh, ROWS, QKV_N, D_MODEL);
    // attention -> half z
    attn_h_kernel<<<dim3(SEQ / 128, BATCH * N_HEADS), 256, ATTN_SMEM>>>(qkvh, zh);
    // O projection + residual -> float mid
    gemm_h<0,1,0><<<dim3(D_MODEL / 128, ROWS / 128), 256, GH_SMEM>>>(
        zh, woh, bO, resid_pre, mid, ROWS, D_MODEL, D_MODEL);
    // LN2 -> half
    ln_kernel_h<<<ROWS, 256>>>(mid, ln2w, ln2b, x2h);
    // MLP up + gelu -> half
    gemm_h<1,0,1><<<dim3(D_MLP / 128, ROWS / 128), 256, GH_SMEM>>>(
        x2h, winh, bin, nullptr, hidh, ROWS, D_MLP, D_MODEL);
    // MLP down + residual -> float out
    gemm_h<0,1,0><<<dim3(D_MODEL / 128, ROWS / 128), 256, GH_SMEM>>>(
        hidh, wouth, bout, mid, out, ROWS, D_MODEL, D_MLP);
}

// round 8
// speedup vs baseline: 1.4969x; 1.4969x over previous
#include <cuda_runtime.h>
#include <cuda_fp16.h>
#include <math.h>
#include <stdint.h>

// ---------------- problem constants ----------------
#define D_MODEL 768
#define N_HEADS 12
#define D_HEAD  64
#define D_MLP   3072
#define BATCH   2
#define SEQ     2048
#define ROWS    (BATCH*SEQ)          // 4096
#define QKV_N   (3*D_MODEL)          // 2304

// ---------------- device scratch ----------------
__device__ __half g_x1h   [ROWS * D_MODEL];
__device__ __half g_qkvh  [ROWS * QKV_N];
__device__ __half g_zh    [ROWS * D_MODEL];
__device__ float  g_mid   [ROWS * D_MODEL];
__device__ __half g_x2h   [ROWS * D_MODEL];
__device__ __half g_hidh  [ROWS * D_MLP];
__device__ __half g_wqkvh [D_MODEL * QKV_N];
__device__ float  g_bqkv  [QKV_N];
__device__ __half g_woh   [D_MODEL * D_MODEL];
__device__ __half g_winh  [D_MODEL * D_MLP];
__device__ __half g_wouth [D_MLP * D_MODEL];

// ---------------- helpers ----------------
__device__ __forceinline__ uint32_t smem_u32(const void* p) {
    uint32_t a;
    asm("{ .reg .u64 t; cvta.to.shared.u64 t, %1; cvt.u32.u64 %0, t; }" : "=r"(a) : "l"(p));
    return a;
}
__device__ __forceinline__ float fast_tanh(float x) {
    float y; asm("tanh.approx.f32 %0, %1;" : "=f"(y) : "f"(x)); return y;
}
__device__ __forceinline__ float gelu_new_f(float x) {
    const float c = 0.7978845608028654f;
    float x3 = x * x * x;
    return 0.5f * x * (1.0f + fast_tanh(c * (x + 0.044715f * x3)));
}
__device__ __forceinline__ void mma_f16(float& c0, float& c1, float& c2, float& c3,
                                        uint32_t a0, uint32_t a1, uint32_t a2, uint32_t a3,
                                        uint32_t b0, uint32_t b1) {
    asm volatile(
        "mma.sync.aligned.m16n8k16.row.col.f32.f16.f16.f32 "
        "{%0,%1,%2,%3}, {%4,%5,%6,%7}, {%8,%9}, {%0,%1,%2,%3};\n"
        : "+f"(c0), "+f"(c1), "+f"(c2), "+f"(c3)
        : "r"(a0), "r"(a1), "r"(a2), "r"(a3), "r"(b0), "r"(b1));
}
__device__ __forceinline__ void ldm_x4(uint32_t& r0, uint32_t& r1, uint32_t& r2, uint32_t& r3,
                                       uint32_t a) {
    asm volatile("ldmatrix.sync.aligned.m8n8.x4.shared.b16 {%0,%1,%2,%3}, [%4];"
                 : "=r"(r0), "=r"(r1), "=r"(r2), "=r"(r3) : "r"(a));
}
__device__ __forceinline__ void ldm_x4t(uint32_t& r0, uint32_t& r1, uint32_t& r2, uint32_t& r3,
                                        uint32_t a) {
    asm volatile("ldmatrix.sync.aligned.m8n8.x4.trans.shared.b16 {%0,%1,%2,%3}, [%4];"
                 : "=r"(r0), "=r"(r1), "=r"(r2), "=r"(r3) : "r"(a));
}
__device__ __forceinline__ void cp16(uint32_t dst, const void* src) {
    asm volatile("cp.async.cg.shared.global [%0], [%1], 16;" :: "r"(dst), "l"(src));
}
#define CP_COMMIT() asm volatile("cp.async.commit_group;" ::: "memory")
#define CP_WAIT1()  asm volatile("cp.async.wait_group 1;" ::: "memory")
#define CP_WAIT0()  asm volatile("cp.async.wait_group 0;" ::: "memory")

__device__ __forceinline__ uint32_t h2u(__half2 h) { return *(uint32_t*)&h; }

__device__ __forceinline__ float block_sum256(float v) {
    __shared__ float red[8];
    __shared__ float total;
    #pragma unroll
    for (int m = 16; m >= 1; m >>= 1) v += __shfl_xor_sync(0xffffffffu, v, m);
    int w = threadIdx.x >> 5;
    if ((threadIdx.x & 31) == 0) red[w] = v;
    __syncthreads();
    if (threadIdx.x < 8) {
        float t = red[threadIdx.x];
        t += __shfl_xor_sync(0xffu, t, 4);
        t += __shfl_xor_sync(0xffu, t, 2);
        t += __shfl_xor_sync(0xffu, t, 1);
        if (threadIdx.x == 0) total = t;
    }
    __syncthreads();
    return total;
}

// ---------------- weight prep -----------------------------------------------------
__global__ void pack_qkv_h(const float* __restrict__ WQ, const float* __restrict__ WK,
                           const float* __restrict__ WV, const float* __restrict__ bQ,
                           const float* __restrict__ bK, const float* __restrict__ bV,
                           __half* __restrict__ Wp, float* __restrict__ bp) {
    int idx = blockIdx.x * blockDim.x + threadIdx.x;
    if (idx < D_MODEL * QKV_N) {
        int e = idx / QKV_N;
        int col = idx - e * QKV_N;
        int which = col / D_MODEL;
        int c = col - which * D_MODEL;
        int n = c >> 6;
        int hd = c & 63;
        const float* W = (which == 0) ? WQ : (which == 1) ? WK : WV;
        Wp[idx] = __float2half_rn(W[((size_t)n * D_MODEL + e) * D_HEAD + hd]);
    }
    if (idx < QKV_N) {
        int which = idx / D_MODEL;
        int c = idx - which * D_MODEL;
        const float* bb = (which == 0) ? bQ : (which == 1) ? bK : bV;
        bp[idx] = bb[c];
    }
}

__global__ void f2h(const float* __restrict__ s, __half* __restrict__ d, int n8) {
    int i = blockIdx.x * 256 + threadIdx.x;
    if (i < n8) {
        float4 v0 = *(const float4*)(s + (size_t)i * 8);
        float4 v1 = *(const float4*)(s + (size_t)i * 8 + 4);
        __half2 h[4];
        h[0] = __floats2half2_rn(v0.x, v0.y);
        h[1] = __floats2half2_rn(v0.z, v0.w);
        h[2] = __floats2half2_rn(v1.x, v1.y);
        h[3] = __floats2half2_rn(v1.z, v1.w);
        *(uint4*)(d + (size_t)i * 8) = *(uint4*)h;
    }
}

// ---------------- layernorm: fp32 in, fp16 out ----------------------------------
__global__ void ln_kernel_h(const float* __restrict__ x, const float* __restrict__ w,
                            const float* __restrict__ b, __half* __restrict__ y) {
    int row = blockIdx.x;
    const float* xr = x + (size_t)row * D_MODEL;
    __half* yr = y + (size_t)row * D_MODEL;
    int tid = threadIdx.x;
    float v0 = xr[tid], v1 = xr[tid + 256], v2 = xr[tid + 512];
    float s = block_sum256(v0 + v1 + v2);
    float mean = s * (1.0f / D_MODEL);
    float d0 = v0 - mean, d1 = v1 - mean, d2 = v2 - mean;
    float sq = block_sum256(d0 * d0 + d1 * d1 + d2 * d2);
    float rstd = rsqrtf(sq * (1.0f / D_MODEL) + 1e-5f);
    yr[tid]       = __float2half_rn(d0 * rstd * w[tid]       + b[tid]);
    yr[tid + 256] = __float2half_rn(d1 * rstd * w[tid + 256] + b[tid + 256]);
    yr[tid + 512] = __float2half_rn(d2 * rstd * w[tid + 512] + b[tid + 512]);
}

// ---------------- fp16 tensor-core GEMM (unchanged from R6) ----------------------
#define GH_STG 32768
#define GH_SMEM (3 * GH_STG)

template<int GELU, int RES, int OUTH>
__global__ __launch_bounds__(256, 2) void gemm_h(
        const __half* __restrict__ A, const __half* __restrict__ B,
        const float* __restrict__ bias, const float* __restrict__ res,
        void* __restrict__ Cv, int M, int N, int K) {
    extern __shared__ char sm8[];
    const uint32_t sb = smem_u32(sm8);

    const int tid = threadIdx.x;
    const int lane = tid & 31;
    const int wid = tid >> 5;
    const int lr = lane >> 2;
    const int lc = lane & 3;
    const int warp_m = wid & 1;
    const int warp_n = wid >> 1;
    const int bm = blockIdx.y * 128;
    const int bn = blockIdx.x * 128;

    float acc[4][4][4];
    #pragma unroll
    for (int i = 0; i < 4; i++)
        #pragma unroll
        for (int j = 0; j < 4; j++)
            #pragma unroll
            for (int u = 0; u < 4; u++) acc[i][j][u] = 0.0f;

    const int nt = K / 64;

    auto issue = [&](int s, int bk) {
        uint32_t ab = sb + (uint32_t)s * GH_STG;
        #pragma unroll
        for (int i = 0; i < 4; i++) {
            int idx = tid + i * 256;
            int rr = idx >> 3, c = idx & 7;
            cp16(ab + (uint32_t)(rr * 128 + ((c ^ (rr & 7)) * 16)),
                 A + (size_t)(bm + rr) * K + bk + c * 8);
        }
        uint32_t bb = ab + 16384;
        #pragma unroll
        for (int i = 0; i < 4; i++) {
            int idx = tid + i * 256;
            int rr = idx >> 4, c = idx & 15;
            int sc = (c & 8) | ((c ^ rr) & 7);
            cp16(bb + (uint32_t)(rr * 256 + sc * 16),
                 B + (size_t)(bk + rr) * N + bn + c * 8);
        }
    };

    issue(0, 0);  CP_COMMIT();
    issue(1, 64); CP_COMMIT();

    const int j8 = lane >> 3;
    const int li = lane & 7;

    for (int t = 0; t < nt; t++) {
        CP_WAIT1();
        __syncthreads();
        if (t + 2 < nt) issue((t + 2) % 3, (t + 2) * 64);
        CP_COMMIT();

        const uint32_t Ab = sb + (uint32_t)(t % 3) * GH_STG;
        const uint32_t Bb = Ab + 16384;

        #pragma unroll
        for (int ks = 0; ks < 4; ks++) {
            uint32_t a[4][4];
            #pragma unroll
            for (int i = 0; i < 4; i++) {
                int row = warp_m * 64 + i * 16 + (j8 & 1) * 8 + li;
                int chunk = ks * 2 + (j8 >> 1);
                ldm_x4(a[i][0], a[i][1], a[i][2], a[i][3],
                       Ab + (uint32_t)(row * 128 + ((chunk ^ (row & 7)) * 16)));
            }
            uint32_t b[2][4];
            #pragma unroll
            for (int jn = 0; jn < 2; jn++) {
                int krow = ks * 16 + (j8 & 1) * 8 + li;
                int nch = warp_n * 4 + jn * 2 + (j8 >> 1);
                int sc = (nch & 8) | ((nch ^ krow) & 7);
                ldm_x4t(b[jn][0], b[jn][1], b[jn][2], b[jn][3],
                        Bb + (uint32_t)(krow * 256 + sc * 16));
            }
            #pragma unroll
            for (int i = 0; i < 4; i++)
                #pragma unroll
                for (int n8 = 0; n8 < 4; n8++) {
                    int jn = n8 >> 1, sub = n8 & 1;
                    mma_f16(acc[i][n8][0], acc[i][n8][1], acc[i][n8][2], acc[i][n8][3],
                            a[i][0], a[i][1], a[i][2], a[i][3],
                            b[jn][sub * 2], b[jn][sub * 2 + 1]);
                }
        }
        __syncthreads();
    }
    CP_WAIT0();

    float* Cf = (float*)Cv;
    __half* Ch = (__half*)Cv;
    #pragma unroll
    for (int i = 0; i < 4; i++) {
        #pragma unroll
        for (int n8 = 0; n8 < 4; n8++) {
            int r0 = bm + warp_m * 64 + i * 16 + lr;
            int cc = bn + warp_n * 32 + n8 * 8 + lc * 2;
            float2 bv = *(const float2*)&bias[cc];
            #pragma unroll
            for (int hrow = 0; hrow < 2; hrow++) {
                int r = r0 + hrow * 8;
                float o0 = acc[i][n8][hrow * 2]     + bv.x;
                float o1 = acc[i][n8][hrow * 2 + 1] + bv.y;
                if (GELU) { o0 = gelu_new_f(o0); o1 = gelu_new_f(o1); }
                if (RES) {
                    float2 rv = *(const float2*)&res[(size_t)r * N + cc];
                    o0 += rv.x; o1 += rv.y;
                }
                if (OUTH) {
                    __half2 h = __floats2half2_rn(o0, o1);
                    *(__half2*)&Ch[(size_t)r * N + cc] = h;
                } else {
                    *(float2*)&Cf[(size_t)r * N + cc] = make_float2(o0, o1);
                }
            }
        }
    }
}

// ---------------- fp16 MMA flash attention, 32-key softmax halves ----------------
// BQ=128, stage=64 keys, inner processing in 32-key halves to cap live registers.
#define AT_Q   16384
#define AT_STG 16384
#define ATTN_SMEM (AT_Q + 3 * AT_STG)   // 64 KB

__global__ __launch_bounds__(256, 2) void attn_h2_kernel(const __half* __restrict__ qkv,
                                                         __half* __restrict__ z) {
    const int qt = (SEQ / 128 - 1) - blockIdx.x;
    const int bh = blockIdx.y;
    const int b = bh / N_HEADS;
    const int h = bh - b * N_HEADS;

    extern __shared__ char sm8[];
    const uint32_t sb = smem_u32(sm8);
    const uint32_t stg = sb + AT_Q;

    const int tid = threadIdx.x;
    const int lane = tid & 31;
    const int wid = tid >> 5;
    const int lr = lane >> 2;
    const int lc = lane & 3;
    const int j8 = lane >> 3;
    const int li = lane & 7;

    const size_t rowbase = (size_t)b * SEQ;
    const __half* qb = qkv + rowbase * QKV_N + h * 64;
    const __half* kb = qb + D_MODEL;
    const __half* vb = qb + 2 * D_MODEL;

    // ---- stage Q (scaled 1/8, exact in half) into swizzled smem ----
    {
        const __half2 sc2 = __floats2half2_rn(0.125f, 0.125f);
        #pragma unroll
        for (int i = 0; i < 4; i++) {
            int idx = tid + i * 256;
            int r = idx >> 3, c = idx & 7;
            uint4 raw = *(const uint4*)(qb + (size_t)(qt * 128 + r) * QKV_N + c * 8);
            __half2* hp = (__half2*)&raw;
            hp[0] = __hmul2(hp[0], sc2); hp[1] = __hmul2(hp[1], sc2);
            hp[2] = __hmul2(hp[2], sc2); hp[3] = __hmul2(hp[3], sc2);
            *(uint4*)(sm8 + r * 128 + ((c ^ (r & 7)) * 16)) = raw;
        }
    }
    __syncthreads();

    // ---- Q register fragments ----
    uint32_t qa[4][4];
    {
        int row = wid * 16 + (j8 & 1) * 8 + li;
        uint32_t rb_ = sb + row * 128;
        #pragma unroll
        for (int ks = 0; ks < 4; ks++) {
            int ch = ks * 2 + (j8 >> 1);
            ldm_x4(qa[ks][0], qa[ks][1], qa[ks][2], qa[ks][3],
                   rb_ + ((ch ^ (row & 7)) * 16));
        }
    }

    const int row0 = qt * 128 + wid * 16 + lr;
    const int row1 = row0 + 8;

    float m0 = -INFINITY, m1 = -INFINITY, l0 = 0.0f, l1 = 0.0f;
    float o[8][4];
    #pragma unroll
    for (int n = 0; n < 8; n++) { o[n][0] = o[n][1] = o[n][2] = o[n][3] = 0.0f; }

    const int nkt = 2 * qt + 2;

    auto issue = [&](int s, int kt) {
        uint32_t base = stg + (uint32_t)s * AT_STG;
        #pragma unroll
        for (int i = 0; i < 2; i++) {
            int idx = tid + i * 256;
            int r = idx >> 3, c = idx & 7;
            uint32_t off = r * 128 + ((c ^ (r & 7)) * 16);
            size_t grow = (size_t)(kt * 64 + r) * QKV_N + c * 8;
            cp16(base + off,        kb + grow);
            cp16(base + 8192 + off, vb + grow);
        }
    };

    issue(0, 0); CP_COMMIT();
    issue(1, 1); CP_COMMIT();

    for (int kt = 0; kt < nkt; kt++) {
        CP_WAIT1();
        __syncthreads();
        if (kt + 2 < nkt) issue((kt + 2) % 3, kt + 2);
        CP_COMMIT();

        const uint32_t Kb = stg + (uint32_t)(kt % 3) * AT_STG;
        const uint32_t Vb = Kb + 8192;
        const bool do_mask = (kt >= 2 * qt);

        #pragma unroll
        for (int hf = 0; hf < 2; hf++) {
            // ---- S = Q K^T for 32 keys (fp16 mma) ----
            float s[4][4];
            #pragma unroll
            for (int n = 0; n < 4; n++) { s[n][0] = s[n][1] = s[n][2] = s[n][3] = 0.0f; }
            #pragma unroll
            for (int ks = 0; ks < 4; ks++) {
                #pragma unroll
                for (int ng = 0; ng < 2; ng++) {
                    int row = hf * 32 + ng * 16 + (j8 & 1) * 8 + li;
                    int ch = ks * 2 + (j8 >> 1);
                    uint32_t k0, k1, k2, k3;
                    ldm_x4(k0, k1, k2, k3, Kb + row * 128 + ((ch ^ (row & 7)) * 16));
                    mma_f16(s[ng * 2][0], s[ng * 2][1], s[ng * 2][2], s[ng * 2][3],
                            qa[ks][0], qa[ks][1], qa[ks][2], qa[ks][3], k0, k2);
                    mma_f16(s[ng * 2 + 1][0], s[ng * 2 + 1][1], s[ng * 2 + 1][2], s[ng * 2 + 1][3],
                            qa[ks][0], qa[ks][1], qa[ks][2], qa[ks][3], k1, k3);
                }
            }

            // ---- causal mask ----
            if (do_mask) {
                const int kbase = kt * 64 + hf * 32 + lc * 2;
                #pragma unroll
                for (int n8 = 0; n8 < 4; n8++) {
                    int key0 = kbase + n8 * 8;
                    int key1 = key0 + 1;
                    if (key0 > row0) s[n8][0] = -1e30f;
                    if (key1 > row0) s[n8][1] = -1e30f;
                    if (key0 > row1) s[n8][2] = -1e30f;
                    if (key1 > row1) s[n8][3] = -1e30f;
                }
            }

            // ---- online softmax (fp32, 32 keys) ----
            float tm0 = -INFINITY, tm1 = -INFINITY;
            #pragma unroll
            for (int n8 = 0; n8 < 4; n8++) {
                tm0 = fmaxf(tm0, fmaxf(s[n8][0], s[n8][1]));
                tm1 = fmaxf(tm1, fmaxf(s[n8][2], s[n8][3]));
            }
            tm0 = fmaxf(tm0, __shfl_xor_sync(0xffffffffu, tm0, 1));
            tm0 = fmaxf(tm0, __shfl_xor_sync(0xffffffffu, tm0, 2));
            tm1 = fmaxf(tm1, __shfl_xor_sync(0xffffffffu, tm1, 1));
            tm1 = fmaxf(tm1, __shfl_xor_sync(0xffffffffu, tm1, 2));
            float nm0 = fmaxf(m0, tm0), nm1 = fmaxf(m1, tm1);
            float a0 = __expf(m0 - nm0), a1 = __expf(m1 - nm1);
            m0 = nm0; m1 = nm1;

            float ts0 = 0.0f, ts1 = 0.0f;
            uint32_t ph[4][2];
            #pragma unroll
            for (int n8 = 0; n8 < 4; n8++) {
                float p0 = __expf(s[n8][0] - nm0);
                float p1 = __expf(s[n8][1] - nm0);
                float p2 = __expf(s[n8][2] - nm1);
                float p3 = __expf(s[n8][3] - nm1);
                ts0 += p0 + p1;
                ts1 += p2 + p3;
                ph[n8][0] = h2u(__floats2half2_rn(p0, p1));
                ph[n8][1] = h2u(__floats2half2_rn(p2, p3));
            }
            ts0 += __shfl_xor_sync(0xffffffffu, ts0, 1);
            ts0 += __shfl_xor_sync(0xffffffffu, ts0, 2);
            ts1 += __shfl_xor_sync(0xffffffffu, ts1, 1);
            ts1 += __shfl_xor_sync(0xffffffffu, ts1, 2);
            l0 = l0 * a0 + ts0;
            l1 = l1 * a1 + ts1;
            #pragma unroll
            for (int n8 = 0; n8 < 8; n8++) {
                o[n8][0] *= a0; o[n8][1] *= a0;
                o[n8][2] *= a1; o[n8][3] *= a1;
            }

            // ---- O += P V (32-key contraction = 2 k16 steps) ----
            #pragma unroll
            for (int ks = 0; ks < 2; ks++) {
                uint32_t pa0 = ph[ks * 2][0];
                uint32_t pa1 = ph[ks * 2][1];
                uint32_t pa2 = ph[ks * 2 + 1][0];
                uint32_t pa3 = ph[ks * 2 + 1][1];
                #pragma unroll
                for (int vg = 0; vg < 4; vg++) {
                    int krow = hf * 32 + ks * 16 + (j8 & 1) * 8 + li;
                    int nch = vg * 2 + (j8 >> 1);
                    uint32_t v0, v1, v2, v3;
                    ldm_x4t(v0, v1, v2, v3, Vb + krow * 128 + ((nch ^ (krow & 7)) * 16));
                    mma_f16(o[vg * 2][0], o[vg * 2][1], o[vg * 2][2], o[vg * 2][3],
                            pa0, pa1, pa2, pa3, v0, v1);
                    mma_f16(o[vg * 2 + 1][0], o[vg * 2 + 1][1], o[vg * 2 + 1][2], o[vg * 2 + 1][3],
                            pa0, pa1, pa2, pa3, v2, v3);
                }
            }
        }
    }
    CP_WAIT0();

    // ---- epilogue ----
    float inv0 = 1.0f / l0, inv1 = 1.0f / l1;
    __half* z0 = z + (rowbase + row0) * D_MODEL + h * 64 + lc * 2;
    __half* z1 = z + (rowbase + row1) * D_MODEL + h * 64 + lc * 2;
    #pragma unroll
    for (int n8 = 0; n8 < 8; n8++) {
        *(__half2*)(z0 + n8 * 8) = __floats2half2_rn(o[n8][0] * inv0, o[n8][1] * inv0);
        *(__half2*)(z1 + n8 * 8) = __floats2half2_rn(o[n8][2] * inv1, o[n8][3] * inv1);
    }
}

// ---------------- launch ----------------
extern "C" void kernel_launch(void* const* d_in, const int* in_sizes, int n_in,
                              void* d_out, int out_size) {
    const float* resid_pre = (const float*)d_in[0];
    const float* WQ   = (const float*)d_in[1];
    const float* bQ   = (const float*)d_in[2];
    const float* WK   = (const float*)d_in[3];
    const float* bK   = (const float*)d_in[4];
    const float* WV   = (const float*)d_in[5];
    const float* bV   = (const float*)d_in[6];
    const float* WO   = (const float*)d_in[7];
    const float* bO   = (const float*)d_in[8];
    const float* ln1w = (const float*)d_in[9];
    const float* ln1b = (const float*)d_in[10];
    const float* ln2w = (const float*)d_in[11];
    const float* ln2b = (const float*)d_in[12];
    const float* Win  = (const float*)d_in[13];
    const float* bin  = (const float*)d_in[14];
    const float* Wout = (const float*)d_in[15];
    const float* bout = (const float*)d_in[16];
    float* out = (float*)d_out;

    __half *x1h, *qkvh, *zh, *x2h, *hidh, *wqkvh, *woh, *winh, *wouth;
    float *mid, *bp;
    cudaGetSymbolAddress((void**)&x1h,    g_x1h);
    cudaGetSymbolAddress((void**)&qkvh,   g_qkvh);
    cudaGetSymbolAddress((void**)&zh,     g_zh);
    cudaGetSymbolAddress((void**)&mid,    g_mid);
    cudaGetSymbolAddress((void**)&x2h,    g_x2h);
    cudaGetSymbolAddress((void**)&hidh,   g_hidh);
    cudaGetSymbolAddress((void**)&wqkvh,  g_wqkvh);
    cudaGetSymbolAddress((void**)&bp,     g_bqkv);
    cudaGetSymbolAddress((void**)&woh,    g_woh);
    cudaGetSymbolAddress((void**)&winh,   g_winh);
    cudaGetSymbolAddress((void**)&wouth,  g_wouth);

    cudaFuncSetAttribute(attn_h2_kernel, cudaFuncAttributeMaxDynamicSharedMemorySize, ATTN_SMEM);
    cudaFuncSetAttribute(gemm_h<0,0,1>, cudaFuncAttributeMaxDynamicSharedMemorySize, GH_SMEM);
    cudaFuncSetAttribute(gemm_h<0,1,0>, cudaFuncAttributeMaxDynamicSharedMemorySize, GH_SMEM);
    cudaFuncSetAttribute(gemm_h<1,0,1>, cudaFuncAttributeMaxDynamicSharedMemorySize, GH_SMEM);

    // weight prep
    pack_qkv_h<<<(D_MODEL * QKV_N + 255) / 256, 256>>>(WQ, WK, WV, bQ, bK, bV, wqkvh, bp);
    f2h<<<(D_MODEL * D_MODEL / 8 + 255) / 256, 256>>>(WO,   woh,   D_MODEL * D_MODEL / 8);
    f2h<<<(D_MODEL * D_MLP   / 8 + 255) / 256, 256>>>(Win,  winh,  D_MODEL * D_MLP / 8);
    f2h<<<(D_MLP   * D_MODEL / 8 + 255) / 256, 256>>>(Wout, wouth, D_MLP * D_MODEL / 8);

    // LN1 -> half
    ln_kernel_h<<<ROWS, 256>>>(resid_pre, ln1w, ln1b, x1h);
    // QKV projection -> half
    gemm_h<0,0,1><<<dim3(QKV_N / 128, ROWS / 128), 256, GH_SMEM>>>(
        x1h, wqkvh, bp, nullptr, qkvh, ROWS, QKV_N, D_MODEL);
    // attention -> half z
    attn_h2_kernel<<<dim3(SEQ / 128, BATCH * N_HEADS), 256, ATTN_SMEM>>>(qkvh, zh);
    // O projection + residual -> float mid
    gemm_h<0,1,0><<<dim3(D_MODEL / 128, ROWS / 128), 256, GH_SMEM>>>(
        zh, woh, bO, resid_pre, mid, ROWS, D_MODEL, D_MODEL);
    // LN2 -> half
    ln_kernel_h<<<ROWS, 256>>>(mid, ln2w, ln2b, x2h);
    // MLP up + gelu -> half
    gemm_h<1,0,1><<<dim3(D_MLP / 128, ROWS / 128), 256, GH_SMEM>>>(
        x2h, winh, bin, nullptr, hidh, ROWS, D_MLP, D_MODEL);
    // MLP down + residual -> float out
    gemm_h<0,1,0><<<dim3(D_MODEL / 128, ROWS / 128), 256, GH_SMEM>>>(
        hidh, wouth, bout, mid, out, ROWS, D_MODEL, D_MLP);
}

// round 9
// speedup vs baseline: 1.5428x; 1.0307x over previous
#include <cuda_runtime.h>
#include <cuda_fp16.h>
#include <math.h>
#include <stdint.h>

// ---------------- problem constants ----------------
#define D_MODEL 768
#define N_HEADS 12
#define D_HEAD  64
#define D_MLP   3072
#define BATCH   2
#define SEQ     2048
#define ROWS    (BATCH*SEQ)          // 4096
#define QKV_N   (3*D_MODEL)          // 2304

// ---------------- device scratch ----------------
__device__ __half g_x1h   [ROWS * D_MODEL];
__device__ __half g_qkvh  [ROWS * QKV_N];
__device__ __half g_zh    [ROWS * D_MODEL];
__device__ float  g_mid   [ROWS * D_MODEL];
__device__ __half g_x2h   [ROWS * D_MODEL];
__device__ __half g_hidh  [ROWS * D_MLP];
__device__ __half g_wqkvh [D_MODEL * QKV_N];
__device__ float  g_bqkv  [QKV_N];
__device__ __half g_woh   [D_MODEL * D_MODEL];
__device__ __half g_winh  [D_MODEL * D_MLP];
__device__ __half g_wouth [D_MLP * D_MODEL];

// ---------------- helpers ----------------
__device__ __forceinline__ uint32_t smem_u32(const void* p) {
    uint32_t a;
    asm("{ .reg .u64 t; cvta.to.shared.u64 t, %1; cvt.u32.u64 %0, t; }" : "=r"(a) : "l"(p));
    return a;
}
__device__ __forceinline__ float fast_tanh(float x) {
    float y; asm("tanh.approx.f32 %0, %1;" : "=f"(y) : "f"(x)); return y;
}
__device__ __forceinline__ float gelu_new_f(float x) {
    const float c = 0.7978845608028654f;
    float x3 = x * x * x;
    return 0.5f * x * (1.0f + fast_tanh(c * (x + 0.044715f * x3)));
}
__device__ __forceinline__ void mma_f16(float& c0, float& c1, float& c2, float& c3,
                                        uint32_t a0, uint32_t a1, uint32_t a2, uint32_t a3,
                                        uint32_t b0, uint32_t b1) {
    asm volatile(
        "mma.sync.aligned.m16n8k16.row.col.f32.f16.f16.f32 "
        "{%0,%1,%2,%3}, {%4,%5,%6,%7}, {%8,%9}, {%0,%1,%2,%3};\n"
        : "+f"(c0), "+f"(c1), "+f"(c2), "+f"(c3)
        : "r"(a0), "r"(a1), "r"(a2), "r"(a3), "r"(b0), "r"(b1));
}
__device__ __forceinline__ void ldm_x4(uint32_t& r0, uint32_t& r1, uint32_t& r2, uint32_t& r3,
                                       uint32_t a) {
    asm volatile("ldmatrix.sync.aligned.m8n8.x4.shared.b16 {%0,%1,%2,%3}, [%4];"
                 : "=r"(r0), "=r"(r1), "=r"(r2), "=r"(r3) : "r"(a));
}
__device__ __forceinline__ void ldm_x4t(uint32_t& r0, uint32_t& r1, uint32_t& r2, uint32_t& r3,
                                        uint32_t a) {
    asm volatile("ldmatrix.sync.aligned.m8n8.x4.trans.shared.b16 {%0,%1,%2,%3}, [%4];"
                 : "=r"(r0), "=r"(r1), "=r"(r2), "=r"(r3) : "r"(a));
}
__device__ __forceinline__ void cp16(uint32_t dst, const void* src) {
    asm volatile("cp.async.cg.shared.global [%0], [%1], 16;" :: "r"(dst), "l"(src));
}
#define CP_COMMIT() asm volatile("cp.async.commit_group;" ::: "memory")
#define CP_WAIT1()  asm volatile("cp.async.wait_group 1;" ::: "memory")
#define CP_WAIT0()  asm volatile("cp.async.wait_group 0;" ::: "memory")

__device__ __forceinline__ uint32_t h2u(__half2 h) { return *(uint32_t*)&h; }

// combined (sum, sumsq) block reduction for 256 threads
__device__ __forceinline__ float2 block_sum2_256(float a, float b) {
    __shared__ float reda[8], redb[8];
    __shared__ float2 total;
    #pragma unroll
    for (int m = 16; m >= 1; m >>= 1) {
        a += __shfl_xor_sync(0xffffffffu, a, m);
        b += __shfl_xor_sync(0xffffffffu, b, m);
    }
    int w = threadIdx.x >> 5;
    if ((threadIdx.x & 31) == 0) { reda[w] = a; redb[w] = b; }
    __syncthreads();
    if (threadIdx.x < 8) {
        float ta = reda[threadIdx.x], tb = redb[threadIdx.x];
        #pragma unroll
        for (int m = 4; m >= 1; m >>= 1) {
            ta += __shfl_xor_sync(0xffu, ta, m);
            tb += __shfl_xor_sync(0xffu, tb, m);
        }
        if (threadIdx.x == 0) total = make_float2(ta, tb);
    }
    __syncthreads();
    return total;
}

// ---------------- weight prep -----------------------------------------------------
__global__ void pack_qkv_h(const float* __restrict__ WQ, const float* __restrict__ WK,
                           const float* __restrict__ WV, const float* __restrict__ bQ,
                           const float* __restrict__ bK, const float* __restrict__ bV,
                           __half* __restrict__ Wp, float* __restrict__ bp) {
    int idx = blockIdx.x * blockDim.x + threadIdx.x;
    if (idx < D_MODEL * QKV_N) {
        int e = idx / QKV_N;
        int col = idx - e * QKV_N;
        int which = col / D_MODEL;
        int c = col - which * D_MODEL;
        int n = c >> 6;
        int hd = c & 63;
        const float* W = (which == 0) ? WQ : (which == 1) ? WK : WV;
        Wp[idx] = __float2half_rn(W[((size_t)n * D_MODEL + e) * D_HEAD + hd]);
    }
    if (idx < QKV_N) {
        int which = idx / D_MODEL;
        int c = idx - which * D_MODEL;
        const float* bb = (which == 0) ? bQ : (which == 1) ? bK : bV;
        bp[idx] = bb[c];
    }
}

// fp32 -> fp16, 32 elements per thread (4 independent 16B-load pairs)
__global__ void f2h4(const float* __restrict__ s, __half* __restrict__ d, int n32) {
    int i = blockIdx.x * 256 + threadIdx.x;
    if (i < n32) {
        size_t base = (size_t)i * 32;
        float4 v[8];
        #pragma unroll
        for (int u = 0; u < 8; u++) v[u] = *(const float4*)(s + base + u * 4);
        #pragma unroll
        for (int u = 0; u < 4; u++) {
            __half2 h[4];
            h[0] = __floats2half2_rn(v[u*2].x,   v[u*2].y);
            h[1] = __floats2half2_rn(v[u*2].z,   v[u*2].w);
            h[2] = __floats2half2_rn(v[u*2+1].x, v[u*2+1].y);
            h[3] = __floats2half2_rn(v[u*2+1].z, v[u*2+1].w);
            *(uint4*)(d + base + u * 8) = *(uint4*)h;
        }
    }
}

// ---------------- layernorm: fp32 in, fp16 out (single-pass) ---------------------
__global__ void ln_kernel_h(const float* __restrict__ x, const float* __restrict__ w,
                            const float* __restrict__ b, __half* __restrict__ y) {
    int row = blockIdx.x;
    const float* xr = x + (size_t)row * D_MODEL;
    __half* yr = y + (size_t)row * D_MODEL;
    int tid = threadIdx.x;
    float v0 = xr[tid], v1 = xr[tid + 256], v2 = xr[tid + 512];
    float2 ss = block_sum2_256(v0 + v1 + v2, v0 * v0 + v1 * v1 + v2 * v2);
    float mean = ss.x * (1.0f / D_MODEL);
    float var = ss.y * (1.0f / D_MODEL) - mean * mean;
    float rstd = rsqrtf(var + 1e-5f);
    yr[tid]       = __float2half_rn((v0 - mean) * rstd * w[tid]       + b[tid]);
    yr[tid + 256] = __float2half_rn((v1 - mean) * rstd * w[tid + 256] + b[tid + 256]);
    yr[tid + 512] = __float2half_rn((v2 - mean) * rstd * w[tid + 512] + b[tid + 512]);
}

// ---------------- fp16 tensor-core GEMM, BM=128 (unchanged from R6) ---------------
#define GH_STG 32768
#define GH_SMEM (3 * GH_STG)

template<int GELU, int RES, int OUTH>
__global__ __launch_bounds__(256, 2) void gemm_h(
        const __half* __restrict__ A, const __half* __restrict__ B,
        const float* __restrict__ bias, const float* __restrict__ res,
        void* __restrict__ Cv, int M, int N, int K) {
    extern __shared__ char sm8[];
    const uint32_t sb = smem_u32(sm8);

    const int tid = threadIdx.x;
    const int lane = tid & 31;
    const int wid = tid >> 5;
    const int lr = lane >> 2;
    const int lc = lane & 3;
    const int warp_m = wid & 1;
    const int warp_n = wid >> 1;
    const int bm = blockIdx.y * 128;
    const int bn = blockIdx.x * 128;

    float acc[4][4][4];
    #pragma unroll
    for (int i = 0; i < 4; i++)
        #pragma unroll
        for (int j = 0; j < 4; j++)
            #pragma unroll
            for (int u = 0; u < 4; u++) acc[i][j][u] = 0.0f;

    const int nt = K / 64;

    auto issue = [&](int s, int bk) {
        uint32_t ab = sb + (uint32_t)s * GH_STG;
        #pragma unroll
        for (int i = 0; i < 4; i++) {
            int idx = tid + i * 256;
            int rr = idx >> 3, c = idx & 7;
            cp16(ab + (uint32_t)(rr * 128 + ((c ^ (rr & 7)) * 16)),
                 A + (size_t)(bm + rr) * K + bk + c * 8);
        }
        uint32_t bb = ab + 16384;
        #pragma unroll
        for (int i = 0; i < 4; i++) {
            int idx = tid + i * 256;
            int rr = idx >> 4, c = idx & 15;
            int sc = (c & 8) | ((c ^ rr) & 7);
            cp16(bb + (uint32_t)(rr * 256 + sc * 16),
                 B + (size_t)(bk + rr) * N + bn + c * 8);
        }
    };

    issue(0, 0);  CP_COMMIT();
    issue(1, 64); CP_COMMIT();

    const int j8 = lane >> 3;
    const int li = lane & 7;

    for (int t = 0; t < nt; t++) {
        CP_WAIT1();
        __syncthreads();
        if (t + 2 < nt) issue((t + 2) % 3, (t + 2) * 64);
        CP_COMMIT();

        const uint32_t Ab = sb + (uint32_t)(t % 3) * GH_STG;
        const uint32_t Bb = Ab + 16384;

        #pragma unroll
        for (int ks = 0; ks < 4; ks++) {
            uint32_t a[4][4];
            #pragma unroll
            for (int i = 0; i < 4; i++) {
                int row = warp_m * 64 + i * 16 + (j8 & 1) * 8 + li;
                int chunk = ks * 2 + (j8 >> 1);
                ldm_x4(a[i][0], a[i][1], a[i][2], a[i][3],
                       Ab + (uint32_t)(row * 128 + ((chunk ^ (row & 7)) * 16)));
            }
            uint32_t b[2][4];
            #pragma unroll
            for (int jn = 0; jn < 2; jn++) {
                int krow = ks * 16 + (j8 & 1) * 8 + li;
                int nch = warp_n * 4 + jn * 2 + (j8 >> 1);
                int sc = (nch & 8) | ((nch ^ krow) & 7);
                ldm_x4t(b[jn][0], b[jn][1], b[jn][2], b[jn][3],
                        Bb + (uint32_t)(krow * 256 + sc * 16));
            }
            #pragma unroll
            for (int i = 0; i < 4; i++)
                #pragma unroll
                for (int n8 = 0; n8 < 4; n8++) {
                    int jn = n8 >> 1, sub = n8 & 1;
                    mma_f16(acc[i][n8][0], acc[i][n8][1], acc[i][n8][2], acc[i][n8][3],
                            a[i][0], a[i][1], a[i][2], a[i][3],
                            b[jn][sub * 2], b[jn][sub * 2 + 1]);
                }
        }
        __syncthreads();
    }
    CP_WAIT0();

    float* Cf = (float*)Cv;
    __half* Ch = (__half*)Cv;
    #pragma unroll
    for (int i = 0; i < 4; i++) {
        #pragma unroll
        for (int n8 = 0; n8 < 4; n8++) {
            int r0 = bm + warp_m * 64 + i * 16 + lr;
            int cc = bn + warp_n * 32 + n8 * 8 + lc * 2;
            float2 bv = *(const float2*)&bias[cc];
            #pragma unroll
            for (int hrow = 0; hrow < 2; hrow++) {
                int r = r0 + hrow * 8;
                float o0 = acc[i][n8][hrow * 2]     + bv.x;
                float o1 = acc[i][n8][hrow * 2 + 1] + bv.y;
                if (GELU) { o0 = gelu_new_f(o0); o1 = gelu_new_f(o1); }
                if (RES) {
                    float2 rv = *(const float2*)&res[(size_t)r * N + cc];
                    o0 += rv.x; o1 += rv.y;
                }
                if (OUTH) {
                    __half2 h = __floats2half2_rn(o0, o1);
                    *(__half2*)&Ch[(size_t)r * N + cc] = h;
                } else {
                    *(float2*)&Cf[(size_t)r * N + cc] = make_float2(o0, o1);
                }
            }
        }
    }
}

// ---------------- fp16 GEMM, BM=64 x BN=128, 3 CTAs/SM (for N=768 GEMMs) ---------
#define G64_STG 24576                 // A 8KB + B 16KB
#define G64_SMEM (3 * G64_STG)        // 72 KB

template<int GELU, int RES, int OUTH>
__global__ __launch_bounds__(256, 3) void gemm_h64(
        const __half* __restrict__ A, const __half* __restrict__ B,
        const float* __restrict__ bias, const float* __restrict__ res,
        void* __restrict__ Cv, int M, int N, int K) {
    extern __shared__ char sm8[];
    const uint32_t sb = smem_u32(sm8);

    const int tid = threadIdx.x;
    const int lane = tid & 31;
    const int wid = tid >> 5;
    const int lr = lane >> 2;
    const int lc = lane & 3;
    const int warp_m = wid & 1;
    const int warp_n = wid >> 1;
    const int bm = blockIdx.y * 64;
    const int bn = blockIdx.x * 128;

    float acc[2][4][4];
    #pragma unroll
    for (int i = 0; i < 2; i++)
        #pragma unroll
        for (int j = 0; j < 4; j++)
            #pragma unroll
            for (int u = 0; u < 4; u++) acc[i][j][u] = 0.0f;

    const int nt = K / 64;

    auto issue = [&](int s, int bk) {
        uint32_t ab = sb + (uint32_t)s * G64_STG;
        #pragma unroll
        for (int i = 0; i < 2; i++) {
            int idx = tid + i * 256;             // 512 chunks (64 rows x 8)
            int rr = idx >> 3, c = idx & 7;
            cp16(ab + (uint32_t)(rr * 128 + ((c ^ (rr & 7)) * 16)),
                 A + (size_t)(bm + rr) * K + bk + c * 8);
        }
        uint32_t bb = ab + 8192;
        #pragma unroll
        for (int i = 0; i < 4; i++) {
            int idx = tid + i * 256;             // 1024 chunks (64 rows x 16)
            int rr = idx >> 4, c = idx & 15;
            int sc = (c & 8) | ((c ^ rr) & 7);
            cp16(bb + (uint32_t)(rr * 256 + sc * 16),
                 B + (size_t)(bk + rr) * N + bn + c * 8);
        }
    };

    issue(0, 0);  CP_COMMIT();
    issue(1, 64); CP_COMMIT();

    const int j8 = lane >> 3;
    const int li = lane & 7;

    for (int t = 0; t < nt; t++) {
        CP_WAIT1();
        __syncthreads();
        if (t + 2 < nt) issue((t + 2) % 3, (t + 2) * 64);
        CP_COMMIT();

        const uint32_t Ab = sb + (uint32_t)(t % 3) * G64_STG;
        const uint32_t Bb = Ab + 8192;

        #pragma unroll
        for (int ks = 0; ks < 4; ks++) {
            uint32_t a[2][4];
            #pragma unroll
            for (int i = 0; i < 2; i++) {
                int row = warp_m * 32 + i * 16 + (j8 & 1) * 8 + li;
                int chunk = ks * 2 + (j8 >> 1);
                ldm_x4(a[i][0], a[i][1], a[i][2], a[i][3],
                       Ab + (uint32_t)(row * 128 + ((chunk ^ (row & 7)) * 16)));
            }
            uint32_t b[2][4];
            #pragma unroll
            for (int jn = 0; jn < 2; jn++) {
                int krow = ks * 16 + (j8 & 1) * 8 + li;
                int nch = warp_n * 4 + jn * 2 + (j8 >> 1);
                int sc = (nch & 8) | ((nch ^ krow) & 7);
                ldm_x4t(b[jn][0], b[jn][1], b[jn][2], b[jn][3],
                        Bb + (uint32_t)(krow * 256 + sc * 16));
            }
            #pragma unroll
            for (int i = 0; i < 2; i++)
                #pragma unroll
                for (int n8 = 0; n8 < 4; n8++) {
                    int jn = n8 >> 1, sub = n8 & 1;
                    mma_f16(acc[i][n8][0], acc[i][n8][1], acc[i][n8][2], acc[i][n8][3],
                            a[i][0], a[i][1], a[i][2], a[i][3],
                            b[jn][sub * 2], b[jn][sub * 2 + 1]);
                }
        }
        __syncthreads();
    }
    CP_WAIT0();

    float* Cf = (float*)Cv;
    __half* Ch = (__half*)Cv;
    #pragma unroll
    for (int i = 0; i < 2; i++) {
        #pragma unroll
        for (int n8 = 0; n8 < 4; n8++) {
            int r0 = bm + warp_m * 32 + i * 16 + lr;
            int cc = bn + warp_n * 32 + n8 * 8 + lc * 2;
            float2 bv = *(const float2*)&bias[cc];
            #pragma unroll
            for (int hrow = 0; hrow < 2; hrow++) {
                int r = r0 + hrow * 8;
                float o0 = acc[i][n8][hrow * 2]     + bv.x;
                float o1 = acc[i][n8][hrow * 2 + 1] + bv.y;
                if (GELU) { o0 = gelu_new_f(o0); o1 = gelu_new_f(o1); }
                if (RES) {
                    float2 rv = *(const float2*)&res[(size_t)r * N + cc];
                    o0 += rv.x; o1 += rv.y;
                }
                if (OUTH) {
                    __half2 h = __floats2half2_rn(o0, o1);
                    *(__half2*)&Ch[(size_t)r * N + cc] = h;
                } else {
                    *(float2*)&Cf[(size_t)r * N + cc] = make_float2(o0, o1);
                }
            }
        }
    }
}

// ---------------- fp16 MMA flash attention, 32-key softmax halves (R8) -----------
#define AT_Q   16384
#define AT_STG 16384
#define ATTN_SMEM (AT_Q + 3 * AT_STG)   // 64 KB

__global__ __launch_bounds__(256, 2) void attn_h2_kernel(const __half* __restrict__ qkv,
                                                         __half* __restrict__ z) {
    const int qt = (SEQ / 128 - 1) - blockIdx.x;
    const int bh = blockIdx.y;
    const int b = bh / N_HEADS;
    const int h = bh - b * N_HEADS;

    extern __shared__ char sm8[];
    const uint32_t sb = smem_u32(sm8);
    const uint32_t stg = sb + AT_Q;

    const int tid = threadIdx.x;
    const int lane = tid & 31;
    const int wid = tid >> 5;
    const int lr = lane >> 2;
    const int lc = lane & 3;
    const int j8 = lane >> 3;
    const int li = lane & 7;

    const size_t rowbase = (size_t)b * SEQ;
    const __half* qb = qkv + rowbase * QKV_N + h * 64;
    const __half* kb = qb + D_MODEL;
    const __half* vb = qb + 2 * D_MODEL;

    {
        const __half2 sc2 = __floats2half2_rn(0.125f, 0.125f);
        #pragma unroll
        for (int i = 0; i < 4; i++) {
            int idx = tid + i * 256;
            int r = idx >> 3, c = idx & 7;
            uint4 raw = *(const uint4*)(qb + (size_t)(qt * 128 + r) * QKV_N + c * 8);
            __half2* hp = (__half2*)&raw;
            hp[0] = __hmul2(hp[0], sc2); hp[1] = __hmul2(hp[1], sc2);
            hp[2] = __hmul2(hp[2], sc2); hp[3] = __hmul2(hp[3], sc2);
            *(uint4*)(sm8 + r * 128 + ((c ^ (r & 7)) * 16)) = raw;
        }
    }
    __syncthreads();

    uint32_t qa[4][4];
    {
        int row = wid * 16 + (j8 & 1) * 8 + li;
        uint32_t rb_ = sb + row * 128;
        #pragma unroll
        for (int ks = 0; ks < 4; ks++) {
            int ch = ks * 2 + (j8 >> 1);
            ldm_x4(qa[ks][0], qa[ks][1], qa[ks][2], qa[ks][3],
                   rb_ + ((ch ^ (row & 7)) * 16));
        }
    }

    const int row0 = qt * 128 + wid * 16 + lr;
    const int row1 = row0 + 8;

    float m0 = -INFINITY, m1 = -INFINITY, l0 = 0.0f, l1 = 0.0f;
    float o[8][4];
    #pragma unroll
    for (int n = 0; n < 8; n++) { o[n][0] = o[n][1] = o[n][2] = o[n][3] = 0.0f; }

    const int nkt = 2 * qt + 2;

    auto issue = [&](int s, int kt) {
        uint32_t base = stg + (uint32_t)s * AT_STG;
        #pragma unroll
        for (int i = 0; i < 2; i++) {
            int idx = tid + i * 256;
            int r = idx >> 3, c = idx & 7;
            uint32_t off = r * 128 + ((c ^ (r & 7)) * 16);
            size_t grow = (size_t)(kt * 64 + r) * QKV_N + c * 8;
            cp16(base + off,        kb + grow);
            cp16(base + 8192 + off, vb + grow);
        }
    };

    issue(0, 0); CP_COMMIT();
    issue(1, 1); CP_COMMIT();

    for (int kt = 0; kt < nkt; kt++) {
        CP_WAIT1();
        __syncthreads();
        if (kt + 2 < nkt) issue((kt + 2) % 3, kt + 2);
        CP_COMMIT();

        const uint32_t Kb = stg + (uint32_t)(kt % 3) * AT_STG;
        const uint32_t Vb = Kb + 8192;
        const bool do_mask = (kt >= 2 * qt);

        #pragma unroll
        for (int hf = 0; hf < 2; hf++) {
            float s[4][4];
            #pragma unroll
            for (int n = 0; n < 4; n++) { s[n][0] = s[n][1] = s[n][2] = s[n][3] = 0.0f; }
            #pragma unroll
            for (int ks = 0; ks < 4; ks++) {
                #pragma unroll
                for (int ng = 0; ng < 2; ng++) {
                    int row = hf * 32 + ng * 16 + (j8 & 1) * 8 + li;
                    int ch = ks * 2 + (j8 >> 1);
                    uint32_t k0, k1, k2, k3;
                    ldm_x4(k0, k1, k2, k3, Kb + row * 128 + ((ch ^ (row & 7)) * 16));
                    mma_f16(s[ng * 2][0], s[ng * 2][1], s[ng * 2][2], s[ng * 2][3],
                            qa[ks][0], qa[ks][1], qa[ks][2], qa[ks][3], k0, k2);
                    mma_f16(s[ng * 2 + 1][0], s[ng * 2 + 1][1], s[ng * 2 + 1][2], s[ng * 2 + 1][3],
                            qa[ks][0], qa[ks][1], qa[ks][2], qa[ks][3], k1, k3);
                }
            }

            if (do_mask) {
                const int kbase = kt * 64 + hf * 32 + lc * 2;
                #pragma unroll
                for (int n8 = 0; n8 < 4; n8++) {
                    int key0 = kbase + n8 * 8;
                    int key1 = key0 + 1;
                    if (key0 > row0) s[n8][0] = -1e30f;
                    if (key1 > row0) s[n8][1] = -1e30f;
                    if (key0 > row1) s[n8][2] = -1e30f;
                    if (key1 > row1) s[n8][3] = -1e30f;
                }
            }

            float tm0 = -INFINITY, tm1 = -INFINITY;
            #pragma unroll
            for (int n8 = 0; n8 < 4; n8++) {
                tm0 = fmaxf(tm0, fmaxf(s[n8][0], s[n8][1]));
                tm1 = fmaxf(tm1, fmaxf(s[n8][2], s[n8][3]));
            }
            tm0 = fmaxf(tm0, __shfl_xor_sync(0xffffffffu, tm0, 1));
            tm0 = fmaxf(tm0, __shfl_xor_sync(0xffffffffu, tm0, 2));
            tm1 = fmaxf(tm1, __shfl_xor_sync(0xffffffffu, tm1, 1));
            tm1 = fmaxf(tm1, __shfl_xor_sync(0xffffffffu, tm1, 2));
            float nm0 = fmaxf(m0, tm0), nm1 = fmaxf(m1, tm1);
            float a0 = __expf(m0 - nm0), a1 = __expf(m1 - nm1);
            m0 = nm0; m1 = nm1;

            float ts0 = 0.0f, ts1 = 0.0f;
            uint32_t ph[4][2];
            #pragma unroll
            for (int n8 = 0; n8 < 4; n8++) {
                float p0 = __expf(s[n8][0] - nm0);
                float p1 = __expf(s[n8][1] - nm0);
                float p2 = __expf(s[n8][2] - nm1);
                float p3 = __expf(s[n8][3] - nm1);
                ts0 += p0 + p1;
                ts1 += p2 + p3;
                ph[n8][0] = h2u(__floats2half2_rn(p0, p1));
                ph[n8][1] = h2u(__floats2half2_rn(p2, p3));
            }
            ts0 += __shfl_xor_sync(0xffffffffu, ts0, 1);
            ts0 += __shfl_xor_sync(0xffffffffu, ts0, 2);
            ts1 += __shfl_xor_sync(0xffffffffu, ts1, 1);
            ts1 += __shfl_xor_sync(0xffffffffu, ts1, 2);
            l0 = l0 * a0 + ts0;
            l1 = l1 * a1 + ts1;
            #pragma unroll
            for (int n8 = 0; n8 < 8; n8++) {
                o[n8][0] *= a0; o[n8][1] *= a0;
                o[n8][2] *= a1; o[n8][3] *= a1;
            }

            #pragma unroll
            for (int ks = 0; ks < 2; ks++) {
                uint32_t pa0 = ph[ks * 2][0];
                uint32_t pa1 = ph[ks * 2][1];
                uint32_t pa2 = ph[ks * 2 + 1][0];
                uint32_t pa3 = ph[ks * 2 + 1][1];
                #pragma unroll
                for (int vg = 0; vg < 4; vg++) {
                    int krow = hf * 32 + ks * 16 + (j8 & 1) * 8 + li;
                    int nch = vg * 2 + (j8 >> 1);
                    uint32_t v0, v1, v2, v3;
                    ldm_x4t(v0, v1, v2, v3, Vb + krow * 128 + ((nch ^ (krow & 7)) * 16));
                    mma_f16(o[vg * 2][0], o[vg * 2][1], o[vg * 2][2], o[vg * 2][3],
                            pa0, pa1, pa2, pa3, v0, v1);
                    mma_f16(o[vg * 2 + 1][0], o[vg * 2 + 1][1], o[vg * 2 + 1][2], o[vg * 2 + 1][3],
                            pa0, pa1, pa2, pa3, v2, v3);
                }
            }
        }
    }
    CP_WAIT0();

    float inv0 = 1.0f / l0, inv1 = 1.0f / l1;
    __half* z0 = z + (rowbase + row0) * D_MODEL + h * 64 + lc * 2;
    __half* z1 = z + (rowbase + row1) * D_MODEL + h * 64 + lc * 2;
    #pragma unroll
    for (int n8 = 0; n8 < 8; n8++) {
        *(__half2*)(z0 + n8 * 8) = __floats2half2_rn(o[n8][0] * inv0, o[n8][1] * inv0);
        *(__half2*)(z1 + n8 * 8) = __floats2half2_rn(o[n8][2] * inv1, o[n8][3] * inv1);
    }
}

// ---------------- launch ----------------
extern "C" void kernel_launch(void* const* d_in, const int* in_sizes, int n_in,
                              void* d_out, int out_size) {
    const float* resid_pre = (const float*)d_in[0];
    const float* WQ   = (const float*)d_in[1];
    const float* bQ   = (const float*)d_in[2];
    const float* WK   = (const float*)d_in[3];
    const float* bK   = (const float*)d_in[4];
    const float* WV   = (const float*)d_in[5];
    const float* bV   = (const float*)d_in[6];
    const float* WO   = (const float*)d_in[7];
    const float* bO   = (const float*)d_in[8];
    const float* ln1w = (const float*)d_in[9];
    const float* ln1b = (const float*)d_in[10];
    const float* ln2w = (const float*)d_in[11];
    const float* ln2b = (const float*)d_in[12];
    const float* Win  = (const float*)d_in[13];
    const float* bin  = (const float*)d_in[14];
    const float* Wout = (const float*)d_in[15];
    const float* bout = (const float*)d_in[16];
    float* out = (float*)d_out;

    __half *x1h, *qkvh, *zh, *x2h, *hidh, *wqkvh, *woh, *winh, *wouth;
    float *mid, *bp;
    cudaGetSymbolAddress((void**)&x1h,    g_x1h);
    cudaGetSymbolAddress((void**)&qkvh,   g_qkvh);
    cudaGetSymbolAddress((void**)&zh,     g_zh);
    cudaGetSymbolAddress((void**)&mid,    g_mid);
    cudaGetSymbolAddress((void**)&x2h,    g_x2h);
    cudaGetSymbolAddress((void**)&hidh,   g_hidh);
    cudaGetSymbolAddress((void**)&wqkvh,  g_wqkvh);
    cudaGetSymbolAddress((void**)&bp,     g_bqkv);
    cudaGetSymbolAddress((void**)&woh,    g_woh);
    cudaGetSymbolAddress((void**)&winh,   g_winh);
    cudaGetSymbolAddress((void**)&wouth,  g_wouth);

    cudaFuncSetAttribute(attn_h2_kernel, cudaFuncAttributeMaxDynamicSharedMemorySize, ATTN_SMEM);
    cudaFuncSetAttribute(gemm_h<0,0,1>, cudaFuncAttributeMaxDynamicSharedMemorySize, GH_SMEM);
    cudaFuncSetAttribute(gemm_h<1,0,1>, cudaFuncAttributeMaxDynamicSharedMemorySize, GH_SMEM);
    cudaFuncSetAttribute(gemm_h64<0,1,0>, cudaFuncAttributeMaxDynamicSharedMemorySize, G64_SMEM);

    // weight prep
    pack_qkv_h<<<(D_MODEL * QKV_N + 255) / 256, 256>>>(WQ, WK, WV, bQ, bK, bV, wqkvh, bp);
    f2h4<<<(D_MODEL * D_MODEL / 32 + 255) / 256, 256>>>(WO,   woh,   D_MODEL * D_MODEL / 32);
    f2h4<<<(D_MODEL * D_MLP   / 32 + 255) / 256, 256>>>(Win,  winh,  D_MODEL * D_MLP / 32);
    f2h4<<<(D_MLP   * D_MODEL / 32 + 255) / 256, 256>>>(Wout, wouth, D_MLP * D_MODEL / 32);

    // LN1 -> half
    ln_kernel_h<<<ROWS, 256>>>(resid_pre, ln1w, ln1b, x1h);
    // QKV projection -> half
    gemm_h<0,0,1><<<dim3(QKV_N / 128, ROWS / 128), 256, GH_SMEM>>>(
        x1h, wqkvh, bp, nullptr, qkvh, ROWS, QKV_N, D_MODEL);
    // attention -> half z
    attn_h2_kernel<<<dim3(SEQ / 128, BATCH * N_HEADS), 256, ATTN_SMEM>>>(qkvh, zh);
    // O projection + residual -> float mid (BM=64, 3 CTAs/SM: single wave)
    gemm_h64<0,1,0><<<dim3(D_MODEL / 128, ROWS / 64), 256, G64_SMEM>>>(
        zh, woh, bO, resid_pre, mid, ROWS, D_MODEL, D_MODEL);
    // LN2 -> half
    ln_kernel_h<<<ROWS, 256>>>(mid, ln2w, ln2b, x2h);
    // MLP up + gelu -> half
    gemm_h<1,0,1><<<dim3(D_MLP / 128, ROWS / 128), 256, GH_SMEM>>>(
        x2h, winh, bin, nullptr, hidh, ROWS, D_MLP, D_MODEL);
    // MLP down + residual -> float out (BM=64, 3 CTAs/SM: single wave)
    gemm_h64<0,1,0><<<dim3(D_MODEL / 128, ROWS / 64), 256, G64_SMEM>>>(
        hidh, wouth, bout, mid, out, ROWS, D_MODEL, D_MLP);
}

// round 10
// speedup vs baseline: 1.5436x; 1.0005x over previous
#include <cuda_runtime.h>
#include <cuda_fp16.h>
#include <math.h>
#include <stdint.h>

// ---------------- problem constants ----------------
#define D_MODEL 768
#define N_HEADS 12
#define D_HEAD  64
#define D_MLP   3072
#define BATCH   2
#define SEQ     2048
#define ROWS    (BATCH*SEQ)          // 4096
#define QKV_N   (3*D_MODEL)          // 2304

// ---------------- device scratch ----------------
__device__ __half g_x1h   [ROWS * D_MODEL];
__device__ __half g_qkvh  [ROWS * QKV_N];
__device__ __half g_zh    [ROWS * D_MODEL];
__device__ float  g_mid   [ROWS * D_MODEL];
__device__ __half g_x2h   [ROWS * D_MODEL];
__device__ __half g_hidh  [ROWS * D_MLP];
__device__ __half g_wqkvh [D_MODEL * QKV_N];
__device__ float  g_bqkv  [QKV_N];
__device__ __half g_woh   [D_MODEL * D_MODEL];
__device__ __half g_winh  [D_MODEL * D_MLP];
__device__ __half g_wouth [D_MLP * D_MODEL];

// ---------------- helpers ----------------
__device__ __forceinline__ uint32_t smem_u32(const void* p) {
    uint32_t a;
    asm("{ .reg .u64 t; cvta.to.shared.u64 t, %1; cvt.u32.u64 %0, t; }" : "=r"(a) : "l"(p));
    return a;
}
__device__ __forceinline__ float fast_tanh(float x) {
    float y; asm("tanh.approx.f32 %0, %1;" : "=f"(y) : "f"(x)); return y;
}
__device__ __forceinline__ float gelu_new_f(float x) {
    const float c = 0.7978845608028654f;
    float x3 = x * x * x;
    return 0.5f * x * (1.0f + fast_tanh(c * (x + 0.044715f * x3)));
}
__device__ __forceinline__ void mma_f16(float& c0, float& c1, float& c2, float& c3,
                                        uint32_t a0, uint32_t a1, uint32_t a2, uint32_t a3,
                                        uint32_t b0, uint32_t b1) {
    asm volatile(
        "mma.sync.aligned.m16n8k16.row.col.f32.f16.f16.f32 "
        "{%0,%1,%2,%3}, {%4,%5,%6,%7}, {%8,%9}, {%0,%1,%2,%3};\n"
        : "+f"(c0), "+f"(c1), "+f"(c2), "+f"(c3)
        : "r"(a0), "r"(a1), "r"(a2), "r"(a3), "r"(b0), "r"(b1));
}
__device__ __forceinline__ void ldm_x4(uint32_t& r0, uint32_t& r1, uint32_t& r2, uint32_t& r3,
                                       uint32_t a) {
    asm volatile("ldmatrix.sync.aligned.m8n8.x4.shared.b16 {%0,%1,%2,%3}, [%4];"
                 : "=r"(r0), "=r"(r1), "=r"(r2), "=r"(r3) : "r"(a));
}
__device__ __forceinline__ void ldm_x4t(uint32_t& r0, uint32_t& r1, uint32_t& r2, uint32_t& r3,
                                        uint32_t a) {
    asm volatile("ldmatrix.sync.aligned.m8n8.x4.trans.shared.b16 {%0,%1,%2,%3}, [%4];"
                 : "=r"(r0), "=r"(r1), "=r"(r2), "=r"(r3) : "r"(a));
}
__device__ __forceinline__ void cp16(uint32_t dst, const void* src) {
    asm volatile("cp.async.cg.shared.global [%0], [%1], 16;" :: "r"(dst), "l"(src));
}
#define CP_COMMIT() asm volatile("cp.async.commit_group;" ::: "memory")
#define CP_WAIT1()  asm volatile("cp.async.wait_group 1;" ::: "memory")
#define CP_WAIT0()  asm volatile("cp.async.wait_group 0;" ::: "memory")

__device__ __forceinline__ uint32_t h2u(__half2 h) { return *(uint32_t*)&h; }

// combined (sum, sumsq) block reduction for 256 threads
__device__ __forceinline__ float2 block_sum2_256(float a, float b) {
    __shared__ float reda[8], redb[8];
    __shared__ float2 total;
    #pragma unroll
    for (int m = 16; m >= 1; m >>= 1) {
        a += __shfl_xor_sync(0xffffffffu, a, m);
        b += __shfl_xor_sync(0xffffffffu, b, m);
    }
    int w = threadIdx.x >> 5;
    if ((threadIdx.x & 31) == 0) { reda[w] = a; redb[w] = b; }
    __syncthreads();
    if (threadIdx.x < 8) {
        float ta = reda[threadIdx.x], tb = redb[threadIdx.x];
        #pragma unroll
        for (int m = 4; m >= 1; m >>= 1) {
            ta += __shfl_xor_sync(0xffu, ta, m);
            tb += __shfl_xor_sync(0xffu, tb, m);
        }
        if (threadIdx.x == 0) total = make_float2(ta, tb);
    }
    __syncthreads();
    return total;
}

// ---------------- weight prep -----------------------------------------------------
// vectorized QKV pack: each thread converts 8 contiguous hd values.
// chunks = 3 * 12 * 768 * 8 = 221184
__global__ void pack_qkv_h8(const float* __restrict__ WQ, const float* __restrict__ WK,
                            const float* __restrict__ WV, const float* __restrict__ bQ,
                            const float* __restrict__ bK, const float* __restrict__ bV,
                            __half* __restrict__ Wp, float* __restrict__ bp) {
    int idx = blockIdx.x * blockDim.x + threadIdx.x;
    const int NCHUNK = 3 * N_HEADS * D_MODEL * 8;
    if (idx < NCHUNK) {
        int hd = (idx & 7) * 8;
        int t  = idx >> 3;
        int e  = t % D_MODEL;
        int t2 = t / D_MODEL;
        int n  = t2 % N_HEADS;
        int which = t2 / N_HEADS;
        const float* W = (which == 0) ? WQ : (which == 1) ? WK : WV;
        const float* src = W + ((size_t)n * D_MODEL + e) * D_HEAD + hd;
        float4 v0 = *(const float4*)(src);
        float4 v1 = *(const float4*)(src + 4);
        __half2 h[4];
        h[0] = __floats2half2_rn(v0.x, v0.y);
        h[1] = __floats2half2_rn(v0.z, v0.w);
        h[2] = __floats2half2_rn(v1.x, v1.y);
        h[3] = __floats2half2_rn(v1.z, v1.w);
        *(uint4*)(Wp + (size_t)e * QKV_N + which * D_MODEL + n * D_HEAD + hd) = *(uint4*)h;
    }
    if (idx < QKV_N) {
        int which = idx / D_MODEL;
        int c = idx - which * D_MODEL;
        const float* bb = (which == 0) ? bQ : (which == 1) ? bK : bV;
        bp[idx] = bb[c];
    }
}

__global__ void f2h(const float* __restrict__ s, __half* __restrict__ d, int n8) {
    int i = blockIdx.x * 256 + threadIdx.x;
    if (i < n8) {
        float4 v0 = *(const float4*)(s + (size_t)i * 8);
        float4 v1 = *(const float4*)(s + (size_t)i * 8 + 4);
        __half2 h[4];
        h[0] = __floats2half2_rn(v0.x, v0.y);
        h[1] = __floats2half2_rn(v0.z, v0.w);
        h[2] = __floats2half2_rn(v1.x, v1.y);
        h[3] = __floats2half2_rn(v1.z, v1.w);
        *(uint4*)(d + (size_t)i * 8) = *(uint4*)h;
    }
}

// ---------------- layernorm: fp32 in, fp16 out (single-pass) ---------------------
__global__ void ln_kernel_h(const float* __restrict__ x, const float* __restrict__ w,
                            const float* __restrict__ b, __half* __restrict__ y) {
    int row = blockIdx.x;
    const float* xr = x + (size_t)row * D_MODEL;
    __half* yr = y + (size_t)row * D_MODEL;
    int tid = threadIdx.x;
    float v0 = xr[tid], v1 = xr[tid + 256], v2 = xr[tid + 512];
    float2 ss = block_sum2_256(v0 + v1 + v2, v0 * v0 + v1 * v1 + v2 * v2);
    float mean = ss.x * (1.0f / D_MODEL);
    float var = ss.y * (1.0f / D_MODEL) - mean * mean;
    float rstd = rsqrtf(var + 1e-5f);
    yr[tid]       = __float2half_rn((v0 - mean) * rstd * w[tid]       + b[tid]);
    yr[tid + 256] = __float2half_rn((v1 - mean) * rstd * w[tid + 256] + b[tid + 256]);
    yr[tid + 512] = __float2half_rn((v2 - mean) * rstd * w[tid + 512] + b[tid + 512]);
}

// ---------------- fp16 GEMM, BM=64 x BN=128, 3 CTAs/SM ---------------------------
#define G64_STG 24576                 // A 8KB + B 16KB
#define G64_SMEM (3 * G64_STG)        // 72 KB

template<int GELU, int RES, int OUTH>
__global__ __launch_bounds__(256, 3) void gemm_h64(
        const __half* __restrict__ A, const __half* __restrict__ B,
        const float* __restrict__ bias, const float* __restrict__ res,
        void* __restrict__ Cv, int M, int N, int K) {
    extern __shared__ char sm8[];
    const uint32_t sb = smem_u32(sm8);

    const int tid = threadIdx.x;
    const int lane = tid & 31;
    const int wid = tid >> 5;
    const int lr = lane >> 2;
    const int lc = lane & 3;
    const int warp_m = wid & 1;
    const int warp_n = wid >> 1;
    const int bm = blockIdx.y * 64;
    const int bn = blockIdx.x * 128;

    float acc[2][4][4];
    #pragma unroll
    for (int i = 0; i < 2; i++)
        #pragma unroll
        for (int j = 0; j < 4; j++)
            #pragma unroll
            for (int u = 0; u < 4; u++) acc[i][j][u] = 0.0f;

    const int nt = K / 64;

    auto issue = [&](int s, int bk) {
        uint32_t ab = sb + (uint32_t)s * G64_STG;
        #pragma unroll
        for (int i = 0; i < 2; i++) {
            int idx = tid + i * 256;
            int rr = idx >> 3, c = idx & 7;
            cp16(ab + (uint32_t)(rr * 128 + ((c ^ (rr & 7)) * 16)),
                 A + (size_t)(bm + rr) * K + bk + c * 8);
        }
        uint32_t bb = ab + 8192;
        #pragma unroll
        for (int i = 0; i < 4; i++) {
            int idx = tid + i * 256;
            int rr = idx >> 4, c = idx & 15;
            int sc = (c & 8) | ((c ^ rr) & 7);
            cp16(bb + (uint32_t)(rr * 256 + sc * 16),
                 B + (size_t)(bk + rr) * N + bn + c * 8);
        }
    };

    issue(0, 0);  CP_COMMIT();
    issue(1, 64); CP_COMMIT();

    const int j8 = lane >> 3;
    const int li = lane & 7;

    for (int t = 0; t < nt; t++) {
        CP_WAIT1();
        __syncthreads();
        if (t + 2 < nt) issue((t + 2) % 3, (t + 2) * 64);
        CP_COMMIT();

        const uint32_t Ab = sb + (uint32_t)(t % 3) * G64_STG;
        const uint32_t Bb = Ab + 8192;

        #pragma unroll
        for (int ks = 0; ks < 4; ks++) {
            uint32_t a[2][4];
            #pragma unroll
            for (int i = 0; i < 2; i++) {
                int row = warp_m * 32 + i * 16 + (j8 & 1) * 8 + li;
                int chunk = ks * 2 + (j8 >> 1);
                ldm_x4(a[i][0], a[i][1], a[i][2], a[i][3],
                       Ab + (uint32_t)(row * 128 + ((chunk ^ (row & 7)) * 16)));
            }
            uint32_t b[2][4];
            #pragma unroll
            for (int jn = 0; jn < 2; jn++) {
                int krow = ks * 16 + (j8 & 1) * 8 + li;
                int nch = warp_n * 4 + jn * 2 + (j8 >> 1);
                int sc = (nch & 8) | ((nch ^ krow) & 7);
                ldm_x4t(b[jn][0], b[jn][1], b[jn][2], b[jn][3],
                        Bb + (uint32_t)(krow * 256 + sc * 16));
            }
            #pragma unroll
            for (int i = 0; i < 2; i++)
                #pragma unroll
                for (int n8 = 0; n8 < 4; n8++) {
                    int jn = n8 >> 1, sub = n8 & 1;
                    mma_f16(acc[i][n8][0], acc[i][n8][1], acc[i][n8][2], acc[i][n8][3],
                            a[i][0], a[i][1], a[i][2], a[i][3],
                            b[jn][sub * 2], b[jn][sub * 2 + 1]);
                }
        }
        __syncthreads();
    }
    CP_WAIT0();

    float* Cf = (float*)Cv;
    __half* Ch = (__half*)Cv;
    #pragma unroll
    for (int i = 0; i < 2; i++) {
        #pragma unroll
        for (int n8 = 0; n8 < 4; n8++) {
            int r0 = bm + warp_m * 32 + i * 16 + lr;
            int cc = bn + warp_n * 32 + n8 * 8 + lc * 2;
            float2 bv = *(const float2*)&bias[cc];
            #pragma unroll
            for (int hrow = 0; hrow < 2; hrow++) {
                int r = r0 + hrow * 8;
                float o0 = acc[i][n8][hrow * 2]     + bv.x;
                float o1 = acc[i][n8][hrow * 2 + 1] + bv.y;
                if (GELU) { o0 = gelu_new_f(o0); o1 = gelu_new_f(o1); }
                if (RES) {
                    float2 rv = *(const float2*)&res[(size_t)r * N + cc];
                    o0 += rv.x; o1 += rv.y;
                }
                if (OUTH) {
                    __half2 h = __floats2half2_rn(o0, o1);
                    *(__half2*)&Ch[(size_t)r * N + cc] = h;
                } else {
                    *(float2*)&Cf[(size_t)r * N + cc] = make_float2(o0, o1);
                }
            }
        }
    }
}

// ---------------- fp16 MMA flash attention, 32-key softmax halves (R8) -----------
#define AT_Q   16384
#define AT_STG 16384
#define ATTN_SMEM (AT_Q + 3 * AT_STG)   // 64 KB

__global__ __launch_bounds__(256, 2) void attn_h2_kernel(const __half* __restrict__ qkv,
                                                         __half* __restrict__ z) {
    const int qt = (SEQ / 128 - 1) - blockIdx.x;
    const int bh = blockIdx.y;
    const int b = bh / N_HEADS;
    const int h = bh - b * N_HEADS;

    extern __shared__ char sm8[];
    const uint32_t sb = smem_u32(sm8);
    const uint32_t stg = sb + AT_Q;

    const int tid = threadIdx.x;
    const int lane = tid & 31;
    const int wid = tid >> 5;
    const int lr = lane >> 2;
    const int lc = lane & 3;
    const int j8 = lane >> 3;
    const int li = lane & 7;

    const size_t rowbase = (size_t)b * SEQ;
    const __half* qb = qkv + rowbase * QKV_N + h * 64;
    const __half* kb = qb + D_MODEL;
    const __half* vb = qb + 2 * D_MODEL;

    {
        const __half2 sc2 = __floats2half2_rn(0.125f, 0.125f);
        #pragma unroll
        for (int i = 0; i < 4; i++) {
            int idx = tid + i * 256;
            int r = idx >> 3, c = idx & 7;
            uint4 raw = *(const uint4*)(qb + (size_t)(qt * 128 + r) * QKV_N + c * 8);
            __half2* hp = (__half2*)&raw;
            hp[0] = __hmul2(hp[0], sc2); hp[1] = __hmul2(hp[1], sc2);
            hp[2] = __hmul2(hp[2], sc2); hp[3] = __hmul2(hp[3], sc2);
            *(uint4*)(sm8 + r * 128 + ((c ^ (r & 7)) * 16)) = raw;
        }
    }
    __syncthreads();

    uint32_t qa[4][4];
    {
        int row = wid * 16 + (j8 & 1) * 8 + li;
        uint32_t rb_ = sb + row * 128;
        #pragma unroll
        for (int ks = 0; ks < 4; ks++) {
            int ch = ks * 2 + (j8 >> 1);
            ldm_x4(qa[ks][0], qa[ks][1], qa[ks][2], qa[ks][3],
                   rb_ + ((ch ^ (row & 7)) * 16));
        }
    }

    const int row0 = qt * 128 + wid * 16 + lr;
    const int row1 = row0 + 8;

    float m0 = -INFINITY, m1 = -INFINITY, l0 = 0.0f, l1 = 0.0f;
    float o[8][4];
    #pragma unroll
    for (int n = 0; n < 8; n++) { o[n][0] = o[n][1] = o[n][2] = o[n][3] = 0.0f; }

    const int nkt = 2 * qt + 2;

    auto issue = [&](int s, int kt) {
        uint32_t base = stg + (uint32_t)s * AT_STG;
        #pragma unroll
        for (int i = 0; i < 2; i++) {
            int idx = tid + i * 256;
            int r = idx >> 3, c = idx & 7;
            uint32_t off = r * 128 + ((c ^ (r & 7)) * 16);
            size_t grow = (size_t)(kt * 64 + r) * QKV_N + c * 8;
            cp16(base + off,        kb + grow);
            cp16(base + 8192 + off, vb + grow);
        }
    };

    issue(0, 0); CP_COMMIT();
    issue(1, 1); CP_COMMIT();

    for (int kt = 0; kt < nkt; kt++) {
        CP_WAIT1();
        __syncthreads();
        if (kt + 2 < nkt) issue((kt + 2) % 3, kt + 2);
        CP_COMMIT();

        const uint32_t Kb = stg + (uint32_t)(kt % 3) * AT_STG;
        const uint32_t Vb = Kb + 8192;
        const bool do_mask = (kt >= 2 * qt);

        #pragma unroll
        for (int hf = 0; hf < 2; hf++) {
            float s[4][4];
            #pragma unroll
            for (int n = 0; n < 4; n++) { s[n][0] = s[n][1] = s[n][2] = s[n][3] = 0.0f; }
            #pragma unroll
            for (int ks = 0; ks < 4; ks++) {
                #pragma unroll
                for (int ng = 0; ng < 2; ng++) {
                    int row = hf * 32 + ng * 16 + (j8 & 1) * 8 + li;
                    int ch = ks * 2 + (j8 >> 1);
                    uint32_t k0, k1, k2, k3;
                    ldm_x4(k0, k1, k2, k3, Kb + row * 128 + ((ch ^ (row & 7)) * 16));
                    mma_f16(s[ng * 2][0], s[ng * 2][1], s[ng * 2][2], s[ng * 2][3],
                            qa[ks][0], qa[ks][1], qa[ks][2], qa[ks][3], k0, k2);
                    mma_f16(s[ng * 2 + 1][0], s[ng * 2 + 1][1], s[ng * 2 + 1][2], s[ng * 2 + 1][3],
                            qa[ks][0], qa[ks][1], qa[ks][2], qa[ks][3], k1, k3);
                }
            }

            if (do_mask) {
                const int kbase = kt * 64 + hf * 32 + lc * 2;
                #pragma unroll
                for (int n8 = 0; n8 < 4; n8++) {
                    int key0 = kbase + n8 * 8;
                    int key1 = key0 + 1;
                    if (key0 > row0) s[n8][0] = -1e30f;
                    if (key1 > row0) s[n8][1] = -1e30f;
                    if (key0 > row1) s[n8][2] = -1e30f;
                    if (key1 > row1) s[n8][3] = -1e30f;
                }
            }

            float tm0 = -INFINITY, tm1 = -INFINITY;
            #pragma unroll
            for (int n8 = 0; n8 < 4; n8++) {
                tm0 = fmaxf(tm0, fmaxf(s[n8][0], s[n8][1]));
                tm1 = fmaxf(tm1, fmaxf(s[n8][2], s[n8][3]));
            }
            tm0 = fmaxf(tm0, __shfl_xor_sync(0xffffffffu, tm0, 1));
            tm0 = fmaxf(tm0, __shfl_xor_sync(0xffffffffu, tm0, 2));
            tm1 = fmaxf(tm1, __shfl_xor_sync(0xffffffffu, tm1, 1));
            tm1 = fmaxf(tm1, __shfl_xor_sync(0xffffffffu, tm1, 2));
            float nm0 = fmaxf(m0, tm0), nm1 = fmaxf(m1, tm1);
            float a0 = __expf(m0 - nm0), a1 = __expf(m1 - nm1);
            m0 = nm0; m1 = nm1;

            float ts0 = 0.0f, ts1 = 0.0f;
            uint32_t ph[4][2];
            #pragma unroll
            for (int n8 = 0; n8 < 4; n8++) {
                float p0 = __expf(s[n8][0] - nm0);
                float p1 = __expf(s[n8][1] - nm0);
                float p2 = __expf(s[n8][2] - nm1);
                float p3 = __expf(s[n8][3] - nm1);
                ts0 += p0 + p1;
                ts1 += p2 + p3;
                ph[n8][0] = h2u(__floats2half2_rn(p0, p1));
                ph[n8][1] = h2u(__floats2half2_rn(p2, p3));
            }
            ts0 += __shfl_xor_sync(0xffffffffu, ts0, 1);
            ts0 += __shfl_xor_sync(0xffffffffu, ts0, 2);
            ts1 += __shfl_xor_sync(0xffffffffu, ts1, 1);
            ts1 += __shfl_xor_sync(0xffffffffu, ts1, 2);
            l0 = l0 * a0 + ts0;
            l1 = l1 * a1 + ts1;
            #pragma unroll
            for (int n8 = 0; n8 < 8; n8++) {
                o[n8][0] *= a0; o[n8][1] *= a0;
                o[n8][2] *= a1; o[n8][3] *= a1;
            }

            #pragma unroll
            for (int ks = 0; ks < 2; ks++) {
                uint32_t pa0 = ph[ks * 2][0];
                uint32_t pa1 = ph[ks * 2][1];
                uint32_t pa2 = ph[ks * 2 + 1][0];
                uint32_t pa3 = ph[ks * 2 + 1][1];
                #pragma unroll
                for (int vg = 0; vg < 4; vg++) {
                    int krow = hf * 32 + ks * 16 + (j8 & 1) * 8 + li;
                    int nch = vg * 2 + (j8 >> 1);
                    uint32_t v0, v1, v2, v3;
                    ldm_x4t(v0, v1, v2, v3, Vb + krow * 128 + ((nch ^ (krow & 7)) * 16));
                    mma_f16(o[vg * 2][0], o[vg * 2][1], o[vg * 2][2], o[vg * 2][3],
                            pa0, pa1, pa2, pa3, v0, v1);
                    mma_f16(o[vg * 2 + 1][0], o[vg * 2 + 1][1], o[vg * 2 + 1][2], o[vg * 2 + 1][3],
                            pa0, pa1, pa2, pa3, v2, v3);
                }
            }
        }
    }
    CP_WAIT0();

    float inv0 = 1.0f / l0, inv1 = 1.0f / l1;
    __half* z0 = z + (rowbase + row0) * D_MODEL + h * 64 + lc * 2;
    __half* z1 = z + (rowbase + row1) * D_MODEL + h * 64 + lc * 2;
    #pragma unroll
    for (int n8 = 0; n8 < 8; n8++) {
        *(__half2*)(z0 + n8 * 8) = __floats2half2_rn(o[n8][0] * inv0, o[n8][1] * inv0);
        *(__half2*)(z1 + n8 * 8) = __floats2half2_rn(o[n8][2] * inv1, o[n8][3] * inv1);
    }
}

// ---------------- launch ----------------
extern "C" void kernel_launch(void* const* d_in, const int* in_sizes, int n_in,
                              void* d_out, int out_size) {
    const float* resid_pre = (const float*)d_in[0];
    const float* WQ   = (const float*)d_in[1];
    const float* bQ   = (const float*)d_in[2];
    const float* WK   = (const float*)d_in[3];
    const float* bK   = (const float*)d_in[4];
    const float* WV   = (const float*)d_in[5];
    const float* bV   = (const float*)d_in[6];
    const float* WO   = (const float*)d_in[7];
    const float* bO   = (const float*)d_in[8];
    const float* ln1w = (const float*)d_in[9];
    const float* ln1b = (const float*)d_in[10];
    const float* ln2w = (const float*)d_in[11];
    const float* ln2b = (const float*)d_in[12];
    const float* Win  = (const float*)d_in[13];
    const float* bin  = (const float*)d_in[14];
    const float* Wout = (const float*)d_in[15];
    const float* bout = (const float*)d_in[16];
    float* out = (float*)d_out;

    __half *x1h, *qkvh, *zh, *x2h, *hidh, *wqkvh, *woh, *winh, *wouth;
    float *mid, *bp;
    cudaGetSymbolAddress((void**)&x1h,    g_x1h);
    cudaGetSymbolAddress((void**)&qkvh,   g_qkvh);
    cudaGetSymbolAddress((void**)&zh,     g_zh);
    cudaGetSymbolAddress((void**)&mid,    g_mid);
    cudaGetSymbolAddress((void**)&x2h,    g_x2h);
    cudaGetSymbolAddress((void**)&hidh,   g_hidh);
    cudaGetSymbolAddress((void**)&wqkvh,  g_wqkvh);
    cudaGetSymbolAddress((void**)&bp,     g_bqkv);
    cudaGetSymbolAddress((void**)&woh,    g_woh);
    cudaGetSymbolAddress((void**)&winh,   g_winh);
    cudaGetSymbolAddress((void**)&wouth,  g_wouth);

    cudaFuncSetAttribute(attn_h2_kernel, cudaFuncAttributeMaxDynamicSharedMemorySize, ATTN_SMEM);
    cudaFuncSetAttribute(gemm_h64<0,0,1>, cudaFuncAttributeMaxDynamicSharedMemorySize, G64_SMEM);
    cudaFuncSetAttribute(gemm_h64<1,0,1>, cudaFuncAttributeMaxDynamicSharedMemorySize, G64_SMEM);
    cudaFuncSetAttribute(gemm_h64<0,1,0>, cudaFuncAttributeMaxDynamicSharedMemorySize, G64_SMEM);

    // weight prep
    {
        const int NCHUNK = 3 * N_HEADS * D_MODEL * 8;
        pack_qkv_h8<<<(NCHUNK + 255) / 256, 256>>>(WQ, WK, WV, bQ, bK, bV, wqkvh, bp);
    }
    f2h<<<(D_MODEL * D_MODEL / 8 + 255) / 256, 256>>>(WO,   woh,   D_MODEL * D_MODEL / 8);
    f2h<<<(D_MODEL * D_MLP   / 8 + 255) / 256, 256>>>(Win,  winh,  D_MODEL * D_MLP / 8);
    f2h<<<(D_MLP   * D_MODEL / 8 + 255) / 256, 256>>>(Wout, wouth, D_MLP * D_MODEL / 8);

    // LN1 -> half
    ln_kernel_h<<<ROWS, 256>>>(resid_pre, ln1w, ln1b, x1h);
    // QKV projection -> half (BM=64, 3 CTAs/SM)
    gemm_h64<0,0,1><<<dim3(QKV_N / 128, ROWS / 64), 256, G64_SMEM>>>(
        x1h, wqkvh, bp, nullptr, qkvh, ROWS, QKV_N, D_MODEL);
    // attention -> half z
    attn_h2_kernel<<<dim3(SEQ / 128, BATCH * N_HEADS), 256, ATTN_SMEM>>>(qkvh, zh);
    // O projection + residual -> float mid
    gemm_h64<0,1,0><<<dim3(D_MODEL / 128, ROWS / 64), 256, G64_SMEM>>>(
        zh, woh, bO, resid_pre, mid, ROWS, D_MODEL, D_MODEL);
    // LN2 -> half
    ln_kernel_h<<<ROWS, 256>>>(mid, ln2w, ln2b, x2h);
    // MLP up + gelu -> half
    gemm_h64<1,0,1><<<dim3(D_MLP / 128, ROWS / 64), 256, G64_SMEM>>>(
        x2h, winh, bin, nullptr, hidh, ROWS, D_MLP, D_MODEL);
    // MLP down + residual -> float out
    gemm_h64<0,1,0><<<dim3(D_MODEL / 128, ROWS / 64), 256, G64_SMEM>>>(
        hidh, wouth, bout, mid, out, ROWS, D_MODEL, D_MLP);
}